// round 6
// baseline (speedup 1.0000x reference)
#include <cuda_runtime.h>
#include <cuda_bf16.h>
#include <cstdint>

#define B_   16
#define N_   1024
#define E_   1024
#define H_   16
#define D_   64
#define M_   (B_ * N_)        // 16384
#define QKV_N (3 * E_)        // 3072
#define KPP_  (3 * E_)        // tripled K'' = 3072
#define KT_   (KPP_ / 64)     // 48 k-iters of 64

// ---------------------------------------------------------------------------
// Scratch (__device__ globals; no allocations anywhere)
// ---------------------------------------------------------------------------
static __device__ __align__(1024) __nv_bfloat16 g_qh[(size_t)B_ * H_ * N_ * D_];
static __device__ __align__(1024) __nv_bfloat16 g_ql[(size_t)B_ * H_ * N_ * D_];
static __device__ __align__(1024) __nv_bfloat16 g_kh[(size_t)B_ * H_ * N_ * D_];
static __device__ __align__(1024) __nv_bfloat16 g_kl[(size_t)B_ * H_ * N_ * D_];
static __device__ __align__(1024) __nv_bfloat16 g_vth[(size_t)B_ * H_ * D_ * N_];
static __device__ __align__(1024) __nv_bfloat16 g_vtl[(size_t)B_ * H_ * D_ * N_];
static __device__ __align__(1024) __nv_bfloat16 g_at [(size_t)M_ * KPP_];
static __device__ __align__(1024) __nv_bfloat16 g_wqt[(size_t)QKV_N * KPP_];
static __device__ __align__(1024) __nv_bfloat16 g_wpt[(size_t)E_ * KPP_];

// ---------------------------------------------------------------------------
// helpers
// ---------------------------------------------------------------------------
__device__ __forceinline__ uint32_t smem_u32(const void* p) {
    uint32_t a;
    asm("{ .reg .u64 t; cvta.to.shared.u64 t, %1; cvt.u32.u64 %0, t; }"
        : "=r"(a) : "l"(p));
    return a;
}
__device__ __forceinline__ void cp_async16(uint32_t dst, const void* src) {
    asm volatile("cp.async.cg.shared.global [%0], [%1], 16;"
                 :: "r"(dst), "l"(src));
}
__device__ __forceinline__ void cp_commit() {
    asm volatile("cp.async.commit_group;" ::: "memory");
}
__device__ __forceinline__ void ldmatrix_x4(uint32_t* d, uint32_t addr) {
    asm volatile("ldmatrix.sync.aligned.m8n8.x4.shared.b16 {%0,%1,%2,%3}, [%4];"
                 : "=r"(d[0]), "=r"(d[1]), "=r"(d[2]), "=r"(d[3]) : "r"(addr));
}
__device__ __forceinline__ void mma16816(float* c, const uint32_t* a,
                                         uint32_t b0, uint32_t b1) {
    asm volatile(
        "mma.sync.aligned.m16n8k16.row.col.f32.bf16.bf16.f32 "
        "{%0,%1,%2,%3}, {%4,%5,%6,%7}, {%8,%9}, {%0,%1,%2,%3};"
        : "+f"(c[0]), "+f"(c[1]), "+f"(c[2]), "+f"(c[3])
        : "r"(a[0]), "r"(a[1]), "r"(a[2]), "r"(a[3]), "r"(b0), "r"(b1));
}
__device__ __forceinline__ uint32_t packbf2(__nv_bfloat16 lo, __nv_bfloat16 hi) {
    return (uint32_t)__bfloat16_as_ushort(lo)
         | ((uint32_t)__bfloat16_as_ushort(hi) << 16);
}
__device__ __forceinline__ void split_bf(float v, __nv_bfloat16& h, __nv_bfloat16& l) {
    h = __float2bfloat16_rn(v);
    l = __float2bfloat16_rn(v - __bfloat162float(h));
}

// ---------------------------------------------------------------------------
// conv_a: fp32 x [M,1024] -> A'' [M][Ah | Al | Ah] bf16 row-major
// ---------------------------------------------------------------------------
__global__ __launch_bounds__(256) void conv_a_kernel(const float* __restrict__ src)
{
    const int m  = blockIdx.x;
    const int k4 = threadIdx.x << 2;
    float4 v = *(const float4*)(src + (size_t)m * E_ + k4);
    const float f[4] = {v.x, v.y, v.z, v.w};

    __nv_bfloat16 h[4], l[4];
#pragma unroll
    for (int j = 0; j < 4; j++) split_bf(f[j], h[j], l[j]);
    uint2 hi; hi.x = packbf2(h[0], h[1]); hi.y = packbf2(h[2], h[3]);
    uint2 lo; lo.x = packbf2(l[0], l[1]); lo.y = packbf2(l[2], l[3]);

    const size_t rb = (size_t)m * KPP_;
    *(uint2*)&g_at[rb + k4]        = hi;
    *(uint2*)&g_at[rb + 1024 + k4] = lo;
    *(uint2*)&g_at[rb + 2048 + k4] = hi;
}

// ---------------------------------------------------------------------------
// conv_w: W [1024][Ncols] fp32 -> W'' [n][Bh | Bh | Bl] bf16 (k contiguous)
// ---------------------------------------------------------------------------
__global__ __launch_bounds__(256) void conv_w_kernel(
    const float* __restrict__ W, int Ncols, int which)
{
    __nv_bfloat16* dst = which ? g_wpt : g_wqt;
    const int idx = blockIdx.x * 256 + threadIdx.x;
    const int n  = idx >> 8;
    const int k  = (idx & 255) << 2;
    if (n >= Ncols) return;

    float f[4];
#pragma unroll
    for (int j = 0; j < 4; j++)
        f[j] = W[(size_t)(k + j) * Ncols + n];

    __nv_bfloat16 h[4], l[4];
#pragma unroll
    for (int j = 0; j < 4; j++) split_bf(f[j], h[j], l[j]);
    uint2 hi; hi.x = packbf2(h[0], h[1]); hi.y = packbf2(h[2], h[3]);
    uint2 lo; lo.x = packbf2(l[0], l[1]); lo.y = packbf2(l[2], l[3]);

    const size_t rb = (size_t)n * KPP_;
    *(uint2*)&dst[rb + k]        = hi;
    *(uint2*)&dst[rb + 1024 + k] = hi;
    *(uint2*)&dst[rb + 2048 + k] = lo;
}

// ---------------------------------------------------------------------------
// HMMA GEMM: C[M, Ncols] = A''[M,3072] @ W''^T + bias
// CTA 128x128, K-step 64, 4 warps (warp tile 64x64), 3-stage cp.async.
// ONE barrier per k-iter + register double-buffered fragments.
// ---------------------------------------------------------------------------
#define GEMM_SMEM (3 * 32768)

__device__ __forceinline__ void load_tile(
    uint32_t sbase, int stage, int ktile,
    const __nv_bfloat16* A, const __nv_bfloat16* Bt,
    int m0, int n0, int tid)
{
    const char* aSrc = (const char*)(A  + (size_t)m0 * KPP_ + ktile * 64);
    const char* bSrc = (const char*)(Bt + (size_t)n0 * KPP_ + ktile * 64);
    const uint32_t sa = sbase + stage * 32768;
    const uint32_t sbB = sa + 16384;
#pragma unroll
    for (int i = 0; i < 8; i++) {
        const int u = i * 128 + tid;
        const int r = u >> 3, c = u & 7;
        cp_async16(sa + r * 128 + ((c ^ (r & 7)) << 4),
                   aSrc + (size_t)r * (KPP_ * 2) + c * 16);
    }
#pragma unroll
    for (int i = 0; i < 8; i++) {
        const int u = i * 128 + tid;
        const int r = u >> 3, c = u & 7;
        cp_async16(sbB + r * 128 + ((c ^ (r & 7)) << 4),
                   bSrc + (size_t)r * (KPP_ * 2) + c * 16);
    }
    cp_commit();
}

__global__ __launch_bounds__(128) void hmma_gemm_kernel(
    const float* __restrict__ bias, float* __restrict__ out, int mode)
{
    extern __shared__ char smem[];
    const uint32_t sb = smem_u32(smem);

    const __nv_bfloat16* A  = g_at;
    const __nv_bfloat16* Bt = (mode == 0) ? g_wqt : g_wpt;

    const int tid  = threadIdx.x;
    const int lane = tid & 31, wid = tid >> 5;
    const int warp_m = wid & 1, warp_n = wid >> 1;
    const int m0 = blockIdx.y * 128, n0 = blockIdx.x * 128;

    float acc[4][8][4];
#pragma unroll
    for (int i = 0; i < 4; i++)
#pragma unroll
        for (int j = 0; j < 8; j++)
#pragma unroll
            for (int r = 0; r < 4; r++) acc[i][j][r] = 0.f;

    load_tile(sb, 0, 0, A, Bt, m0, n0, tid);
    load_tile(sb, 1, 1, A, Bt, m0, n0, tid);

    const int lane15 = lane & 15, lhalf = lane >> 4;
    const int ra  = warp_m * 64 + lane15;   // A fragment base row (+16*mi)
    const int rbw = warp_n * 64 + lane15;   // B fragment base row (+16*ng)

    for (int kt = 0; kt < KT_; kt++) {
        asm volatile("cp.async.wait_group 1;" ::: "memory");
        __syncthreads();   // data-ready for kt AND safe reuse of stage (kt+2)%3
        if (kt + 2 < KT_)
            load_tile(sb, (kt + 2) % 3, kt + 2, A, Bt, m0, n0, tid);
        else
            cp_commit();   // keep group counting uniform

        const uint32_t sa  = sb + (kt % 3) * 32768;
        const uint32_t sbB = sa + 16384;

        uint32_t afr[2][4][4], bfr[2][4][4];
        // prefetch k-chunk 0 into buffer 0
        {
            const int kc = lhalf;
#pragma unroll
            for (int mi = 0; mi < 4; mi++) {
                const int r = ra + mi * 16;
                ldmatrix_x4(afr[0][mi], sa + r * 128 + ((kc ^ (r & 7)) << 4));
            }
#pragma unroll
            for (int ng = 0; ng < 4; ng++) {
                const int r = rbw + ng * 16;
                ldmatrix_x4(bfr[0][ng], sbB + r * 128 + ((kc ^ (r & 7)) << 4));
            }
        }
#pragma unroll
        for (int kk = 0; kk < 4; kk++) {
            const int cur = kk & 1, nxt = cur ^ 1;
            if (kk < 3) {   // prefetch next k-chunk into alternate buffer
                const int kc = (kk + 1) * 2 + lhalf;
#pragma unroll
                for (int mi = 0; mi < 4; mi++) {
                    const int r = ra + mi * 16;
                    ldmatrix_x4(afr[nxt][mi], sa + r * 128 + ((kc ^ (r & 7)) << 4));
                }
#pragma unroll
                for (int ng = 0; ng < 4; ng++) {
                    const int r = rbw + ng * 16;
                    ldmatrix_x4(bfr[nxt][ng], sbB + r * 128 + ((kc ^ (r & 7)) << 4));
                }
            }
#pragma unroll
            for (int mi = 0; mi < 4; mi++)
#pragma unroll
                for (int nj = 0; nj < 8; nj++)
                    mma16816(acc[mi][nj], afr[cur][mi],
                             bfr[cur][nj >> 1][nj & 1],
                             bfr[cur][nj >> 1][(nj & 1) + 2]);
        }
    }

    // Epilogue
    const int mrow = m0 + warp_m * 64 + (lane >> 2);
    const int ncb  = n0 + warp_n * 64 + (lane & 3) * 2;
#pragma unroll
    for (int mi = 0; mi < 4; mi++) {
#pragma unroll
        for (int nj = 0; nj < 8; nj++) {
            const int c  = ncb + nj * 8;
            const float b0 = bias[c], b1 = bias[c + 1];
            const int r0 = mrow + mi * 16;
            float v00 = acc[mi][nj][0] + b0, v01 = acc[mi][nj][1] + b1;
            float v10 = acc[mi][nj][2] + b0, v11 = acc[mi][nj][3] + b1;
            if (mode == 1) {
                float2 p0; p0.x = v00; p0.y = v01;
                float2 p1; p1.x = v10; p1.y = v11;
                *(float2*)&out[(size_t)r0 * E_ + c] = p0;
                *(float2*)&out[(size_t)(r0 + 8) * E_ + c] = p1;
                continue;
            }
            __nv_bfloat16 h00, l00, h01, l01, h10, l10, h11, l11;
            split_bf(v00, h00, l00); split_bf(v01, h01, l01);
            split_bf(v10, h10, l10); split_bf(v11, h11, l11);
            const int sec = c >> 10, e = c & 1023;
            const int hh = e >> 6, dd = e & 63;
            const int bb = r0 >> 10, nn = r0 & 1023;
            if (sec <= 1) {
                __nv_bfloat16* dh = sec == 0 ? g_qh : g_kh;
                __nv_bfloat16* dl = sec == 0 ? g_ql : g_kl;
                const size_t i0 = (((size_t)bb * H_ + hh) * N_ + nn) * D_ + dd;
                const size_t i1 = i0 + 8 * D_;
                *(uint32_t*)&dh[i0] = packbf2(h00, h01);
                *(uint32_t*)&dl[i0] = packbf2(l00, l01);
                *(uint32_t*)&dh[i1] = packbf2(h10, h11);
                *(uint32_t*)&dl[i1] = packbf2(l10, l11);
            } else {
                const size_t i00 = (((size_t)bb * H_ + hh) * D_ + dd) * N_ + nn;
                g_vth[i00] = h00;          g_vtl[i00] = l00;
                g_vth[i00 + N_] = h01;     g_vtl[i00 + N_] = l01;
                g_vth[i00 + 8] = h10;      g_vtl[i00 + 8] = l10;
                g_vth[i00 + N_ + 8] = h11; g_vtl[i00 + N_ + 8] = l11;
            }
        }
    }
}

// ---------------------------------------------------------------------------
// Flash attention on HMMA. 3-stage pipeline, ONE barrier per kv-iter.
// ---------------------------------------------------------------------------
#define ATT_SMEM (3 * 32768)
// stage layout: Kh @0, Kl @8192, Vh @16384, Vl @24576 (each 64 rows x 128B)

__device__ __forceinline__ void att_load_tile(
    uint32_t st, int kv0,
    const __nv_bfloat16* kh, const __nv_bfloat16* kl,
    const __nv_bfloat16* vh, const __nv_bfloat16* vl, int tid)
{
#pragma unroll
    for (int i = 0; i < 4; i++) {
        const int u = i * 128 + tid;
        const int r = u >> 3, c = u & 7;
        const uint32_t soff = r * 128 + ((c ^ (r & 7)) << 4);
        cp_async16(st + soff,         (const char*)kh + (size_t)(kv0 + r) * 128 + c * 16);
        cp_async16(st + 8192 + soff,  (const char*)kl + (size_t)(kv0 + r) * 128 + c * 16);
        cp_async16(st + 16384 + soff, (const char*)vh + (size_t)r * 2048 + kv0 * 2 + c * 16);
        cp_async16(st + 24576 + soff, (const char*)vl + (size_t)r * 2048 + kv0 * 2 + c * 16);
    }
    cp_commit();
}

__global__ __launch_bounds__(128) void attn_hmma_kernel()
{
    extern __shared__ char smem[];
    const uint32_t sb = smem_u32(smem);

    const int tid = threadIdx.x;
    const int lane = tid & 31, w = tid >> 5;
    const int lane15 = lane & 15, lhalf = lane >> 4;
    const int q0 = blockIdx.x * 64;
    const int h  = blockIdx.y;
    const int b  = blockIdx.z;

    const size_t hb = (size_t)(b * H_ + h) * (N_ * D_);
    const __nv_bfloat16* qh = g_qh + hb;
    const __nv_bfloat16* ql = g_ql + hb;
    const __nv_bfloat16* kh = g_kh + hb;
    const __nv_bfloat16* kl = g_kl + hb;
    const __nv_bfloat16* vh = g_vth + hb;
    const __nv_bfloat16* vl = g_vtl + hb;

    // stage Q in stage-0 area, extract fragments
#pragma unroll
    for (int i = 0; i < 4; i++) {
        const int u = i * 128 + tid;
        const int r = u >> 3, c = u & 7;
        const uint32_t soff = r * 128 + ((c ^ (r & 7)) << 4);
        cp_async16(sb + soff,        (const char*)qh + (size_t)(q0 + r) * 128 + c * 16);
        cp_async16(sb + 8192 + soff, (const char*)ql + (size_t)(q0 + r) * 128 + c * 16);
    }
    cp_commit();
    asm volatile("cp.async.wait_group 0;" ::: "memory");
    __syncthreads();

    uint32_t qfh[4][4], qfl[4][4];
    {
        const int r = w * 16 + lane15;
#pragma unroll
        for (int t = 0; t < 4; t++) {
            const uint32_t soff = r * 128 + (((t * 2 + lhalf) ^ (r & 7)) << 4);
            ldmatrix_x4(qfh[t], sb + soff);
            ldmatrix_x4(qfl[t], sb + 8192 + soff);
        }
    }
    __syncthreads();

    float mstate[2] = {-1e30f, -1e30f};
    float lstate[2] = {0.f, 0.f};
    float oacc[8][4];
#pragma unroll
    for (int j = 0; j < 8; j++)
#pragma unroll
        for (int r = 0; r < 4; r++) oacc[j][r] = 0.f;

    const float cexp = 0.18033688f;   // D^-0.5 * log2(e)

    att_load_tile(sb, 0, kh, kl, vh, vl, tid);
    att_load_tile(sb + 32768, 64, kh, kl, vh, vl, tid);

    for (int t = 0; t < 16; t++) {
        asm volatile("cp.async.wait_group 1;" ::: "memory");
        __syncthreads();   // data-ready for t AND safe reuse of stage (t+2)%3
        if (t + 2 < 16)
            att_load_tile(sb + ((t + 2) % 3) * 32768, (t + 2) * 64, kh, kl, vh, vl, tid);
        else
            cp_commit();

        const uint32_t stK = sb + (t % 3) * 32768;
        const uint32_t stV = stK + 16384;

        float sacc[8][4];
#pragma unroll
        for (int j = 0; j < 8; j++)
#pragma unroll
            for (int r = 0; r < 4; r++) sacc[j][r] = 0.f;

#pragma unroll
        for (int kvg = 0; kvg < 4; kvg++) {
            const int rb = kvg * 16 + lane15;
#pragma unroll
            for (int kk = 0; kk < 4; kk++) {
                const uint32_t soff = rb * 128 + (((kk * 2 + lhalf) ^ (rb & 7)) << 4);
                uint32_t bf[4];
                ldmatrix_x4(bf, stK + soff);
                mma16816(sacc[2 * kvg],     qfh[kk], bf[0], bf[2]);
                mma16816(sacc[2 * kvg + 1], qfh[kk], bf[1], bf[3]);
                mma16816(sacc[2 * kvg],     qfl[kk], bf[0], bf[2]);
                mma16816(sacc[2 * kvg + 1], qfl[kk], bf[1], bf[3]);
                ldmatrix_x4(bf, stK + 8192 + soff);
                mma16816(sacc[2 * kvg],     qfh[kk], bf[0], bf[2]);
                mma16816(sacc[2 * kvg + 1], qfh[kk], bf[1], bf[3]);
            }
        }

#pragma unroll
        for (int rr = 0; rr < 2; rr++) {
            float mx = -1e30f;
#pragma unroll
            for (int j = 0; j < 8; j++)
                mx = fmaxf(mx, fmaxf(sacc[j][rr * 2], sacc[j][rr * 2 + 1]));
            mx = fmaxf(mx, __shfl_xor_sync(0xffffffffu, mx, 1));
            mx = fmaxf(mx, __shfl_xor_sync(0xffffffffu, mx, 2));
            const float mnew  = fmaxf(mstate[rr], mx);
            const float alpha = exp2f((mstate[rr] - mnew) * cexp);
            mstate[rr] = mnew;
            float rs = 0.f;
#pragma unroll
            for (int j = 0; j < 8; j++) {
                const float p0 = exp2f((sacc[j][rr * 2]     - mnew) * cexp);
                const float p1 = exp2f((sacc[j][rr * 2 + 1] - mnew) * cexp);
                sacc[j][rr * 2] = p0; sacc[j][rr * 2 + 1] = p1;
                rs += p0 + p1;
            }
            rs += __shfl_xor_sync(0xffffffffu, rs, 1);
            rs += __shfl_xor_sync(0xffffffffu, rs, 2);
            lstate[rr] = lstate[rr] * alpha + rs;
#pragma unroll
            for (int j = 0; j < 8; j++) {
                oacc[j][rr * 2]     *= alpha;
                oacc[j][rr * 2 + 1] *= alpha;
            }
        }

        uint32_t ph[4][4], pl[4][4];
#pragma unroll
        for (int kk = 0; kk < 4; kk++) {
#pragma unroll
            for (int q = 0; q < 4; q++) {
                const int tile = 2 * kk + (q >> 1);
                const int ri   = (q & 1) * 2;
                const float p0 = sacc[tile][ri], p1 = sacc[tile][ri + 1];
                __nv_bfloat16 h0, l0, h1, l1;
                split_bf(p0, h0, l0); split_bf(p1, h1, l1);
                ph[kk][q] = packbf2(h0, h1);
                pl[kk][q] = packbf2(l0, l1);
            }
        }

#pragma unroll
        for (int dg = 0; dg < 4; dg++) {
            const int rb = dg * 16 + lane15;
#pragma unroll
            for (int kk = 0; kk < 4; kk++) {
                const uint32_t soff = rb * 128 + (((kk * 2 + lhalf) ^ (rb & 7)) << 4);
                uint32_t bf[4];
                ldmatrix_x4(bf, stV + soff);
                mma16816(oacc[2 * dg],     ph[kk], bf[0], bf[2]);
                mma16816(oacc[2 * dg + 1], ph[kk], bf[1], bf[3]);
                mma16816(oacc[2 * dg],     pl[kk], bf[0], bf[2]);
                mma16816(oacc[2 * dg + 1], pl[kk], bf[1], bf[3]);
                ldmatrix_x4(bf, stV + 8192 + soff);
                mma16816(oacc[2 * dg],     ph[kk], bf[0], bf[2]);
                mma16816(oacc[2 * dg + 1], ph[kk], bf[1], bf[3]);
            }
        }
    }

    const float inv0 = 1.f / lstate[0];
    const float inv1 = 1.f / lstate[1];
    const int qrow = q0 + w * 16 + (lane >> 2);
    const size_t m0r = (size_t)(b * N_ + qrow) * KPP_;
    const size_t m1r = m0r + (size_t)8 * KPP_;
    const int colb = h * 64 + 2 * (lane & 3);
#pragma unroll
    for (int j = 0; j < 8; j++) {
        const int col = colb + 8 * j;
        {
            __nv_bfloat16 h0, l0, h1, l1;
            split_bf(oacc[j][0] * inv0, h0, l0);
            split_bf(oacc[j][1] * inv0, h1, l1);
            const uint32_t hi = packbf2(h0, h1), lo = packbf2(l0, l1);
            *(uint32_t*)&g_at[m0r + col]        = hi;
            *(uint32_t*)&g_at[m0r + 1024 + col] = lo;
            *(uint32_t*)&g_at[m0r + 2048 + col] = hi;
        }
        {
            __nv_bfloat16 h0, l0, h1, l1;
            split_bf(oacc[j][2] * inv1, h0, l0);
            split_bf(oacc[j][3] * inv1, h1, l1);
            const uint32_t hi = packbf2(h0, h1), lo = packbf2(l0, l1);
            *(uint32_t*)&g_at[m1r + col]        = hi;
            *(uint32_t*)&g_at[m1r + 1024 + col] = lo;
            *(uint32_t*)&g_at[m1r + 2048 + col] = hi;
        }
    }
}

// ---------------------------------------------------------------------------
extern "C" void kernel_launch(void* const* d_in, const int* in_sizes, int n_in,
                              void* d_out, int out_size)
{
    const float* x  = (const float*)d_in[0];
    const float* Wq = (const float*)d_in[1];
    const float* bq = (const float*)d_in[2];
    const float* Wp = (const float*)d_in[3];
    const float* bp = (const float*)d_in[4];
    float* out = (float*)d_out;

    cudaFuncSetAttribute(hmma_gemm_kernel,
                         cudaFuncAttributeMaxDynamicSharedMemorySize, GEMM_SMEM);
    cudaFuncSetAttribute(attn_hmma_kernel,
                         cudaFuncAttributeMaxDynamicSharedMemorySize, ATT_SMEM);

    conv_a_kernel<<<M_, 256>>>(x);
    conv_w_kernel<<<QKV_N, 256>>>(Wq, QKV_N, 0);
    conv_w_kernel<<<E_, 256>>>(Wp, E_, 1);

    hmma_gemm_kernel<<<dim3(QKV_N / 128, M_ / 128), 128, GEMM_SMEM>>>(bq, out, 0);

    attn_hmma_kernel<<<dim3(N_ / 64, H_, B_), 128, ATT_SMEM>>>();

    hmma_gemm_kernel<<<dim3(E_ / 128, M_ / 128), 128, GEMM_SMEM>>>(bp, out, 1);
}

// round 7
// speedup vs baseline: 1.0008x; 1.0008x over previous
#include <cuda_runtime.h>
#include <cuda_bf16.h>
#include <cstdint>

#define B_   16
#define N_   1024
#define E_   1024
#define H_   16
#define D_   64
#define M_   (B_ * N_)        // 16384
#define QKV_N (3 * E_)        // 3072
#define KPP_  (3 * E_)        // tripled K'' = 3072
#define KT_   (KPP_ / 64)     // 48 k-iters of 64

// ---------------------------------------------------------------------------
// Scratch (__device__ globals; no allocations anywhere)
// ---------------------------------------------------------------------------
static __device__ __align__(1024) __nv_bfloat16 g_qh[(size_t)B_ * H_ * N_ * D_];
static __device__ __align__(1024) __nv_bfloat16 g_ql[(size_t)B_ * H_ * N_ * D_];
static __device__ __align__(1024) __nv_bfloat16 g_kh[(size_t)B_ * H_ * N_ * D_];
static __device__ __align__(1024) __nv_bfloat16 g_kl[(size_t)B_ * H_ * N_ * D_];
static __device__ __align__(1024) __nv_bfloat16 g_vth[(size_t)B_ * H_ * D_ * N_];
static __device__ __align__(1024) __nv_bfloat16 g_vtl[(size_t)B_ * H_ * D_ * N_];
static __device__ __align__(1024) __nv_bfloat16 g_at [(size_t)M_ * KPP_];
static __device__ __align__(1024) __nv_bfloat16 g_wqt[(size_t)QKV_N * KPP_];
static __device__ __align__(1024) __nv_bfloat16 g_wpt[(size_t)E_ * KPP_];

// ---------------------------------------------------------------------------
// helpers
// ---------------------------------------------------------------------------
__device__ __forceinline__ uint32_t smem_u32(const void* p) {
    uint32_t a;
    asm("{ .reg .u64 t; cvta.to.shared.u64 t, %1; cvt.u32.u64 %0, t; }"
        : "=r"(a) : "l"(p));
    return a;
}
__device__ __forceinline__ void cp_async16(uint32_t dst, const void* src) {
    asm volatile("cp.async.cg.shared.global [%0], [%1], 16;"
                 :: "r"(dst), "l"(src));
}
__device__ __forceinline__ void cp_commit() {
    asm volatile("cp.async.commit_group;" ::: "memory");
}
__device__ __forceinline__ void ldmatrix_x4(uint32_t* d, uint32_t addr) {
    asm volatile("ldmatrix.sync.aligned.m8n8.x4.shared.b16 {%0,%1,%2,%3}, [%4];"
                 : "=r"(d[0]), "=r"(d[1]), "=r"(d[2]), "=r"(d[3]) : "r"(addr));
}
__device__ __forceinline__ void mma16816(float* c, const uint32_t* a,
                                         uint32_t b0, uint32_t b1) {
    asm volatile(
        "mma.sync.aligned.m16n8k16.row.col.f32.bf16.bf16.f32 "
        "{%0,%1,%2,%3}, {%4,%5,%6,%7}, {%8,%9}, {%0,%1,%2,%3};"
        : "+f"(c[0]), "+f"(c[1]), "+f"(c[2]), "+f"(c[3])
        : "r"(a[0]), "r"(a[1]), "r"(a[2]), "r"(a[3]), "r"(b0), "r"(b1));
}
__device__ __forceinline__ uint32_t packbf2(__nv_bfloat16 lo, __nv_bfloat16 hi) {
    return (uint32_t)__bfloat16_as_ushort(lo)
         | ((uint32_t)__bfloat16_as_ushort(hi) << 16);
}
__device__ __forceinline__ void split_bf(float v, __nv_bfloat16& h, __nv_bfloat16& l) {
    h = __float2bfloat16_rn(v);
    l = __float2bfloat16_rn(v - __bfloat162float(h));
}

// ---------------------------------------------------------------------------
// conv_a: fp32 x [M,1024] -> A'' [M][Ah | Al | Ah] bf16 row-major
// ---------------------------------------------------------------------------
__global__ __launch_bounds__(256) void conv_a_kernel(const float* __restrict__ src)
{
    const int m  = blockIdx.x;
    const int k4 = threadIdx.x << 2;
    float4 v = *(const float4*)(src + (size_t)m * E_ + k4);
    const float f[4] = {v.x, v.y, v.z, v.w};

    __nv_bfloat16 h[4], l[4];
#pragma unroll
    for (int j = 0; j < 4; j++) split_bf(f[j], h[j], l[j]);
    uint2 hi; hi.x = packbf2(h[0], h[1]); hi.y = packbf2(h[2], h[3]);
    uint2 lo; lo.x = packbf2(l[0], l[1]); lo.y = packbf2(l[2], l[3]);

    const size_t rb = (size_t)m * KPP_;
    *(uint2*)&g_at[rb + k4]        = hi;
    *(uint2*)&g_at[rb + 1024 + k4] = lo;
    *(uint2*)&g_at[rb + 2048 + k4] = hi;
}

// ---------------------------------------------------------------------------
// conv_w: W [1024][Ncols] fp32 -> W'' [n][Bh | Bh | Bl] bf16 (k contiguous)
// ---------------------------------------------------------------------------
__global__ __launch_bounds__(256) void conv_w_kernel(
    const float* __restrict__ W, int Ncols, int which)
{
    __nv_bfloat16* dst = which ? g_wpt : g_wqt;
    const int idx = blockIdx.x * 256 + threadIdx.x;
    const int n  = idx >> 8;
    const int k  = (idx & 255) << 2;
    if (n >= Ncols) return;

    float f[4];
#pragma unroll
    for (int j = 0; j < 4; j++)
        f[j] = W[(size_t)(k + j) * Ncols + n];

    __nv_bfloat16 h[4], l[4];
#pragma unroll
    for (int j = 0; j < 4; j++) split_bf(f[j], h[j], l[j]);
    uint2 hi; hi.x = packbf2(h[0], h[1]); hi.y = packbf2(h[2], h[3]);
    uint2 lo; lo.x = packbf2(l[0], l[1]); lo.y = packbf2(l[2], l[3]);

    const size_t rb = (size_t)n * KPP_;
    *(uint2*)&dst[rb + k]        = hi;
    *(uint2*)&dst[rb + 1024 + k] = hi;
    *(uint2*)&dst[rb + 2048 + k] = lo;
}

// ---------------------------------------------------------------------------
// HMMA GEMM: C[M, Ncols] = A''[M,3072] @ W''^T + bias
// CTA 128x128, K-step 64, 4 warps (warp tile 64x64), 3-stage cp.async.
// ONE barrier per k-iter + register double-buffered fragments.
// ---------------------------------------------------------------------------
#define GEMM_SMEM (3 * 32768)

__device__ __forceinline__ void load_tile(
    uint32_t sbase, int stage, int ktile,
    const __nv_bfloat16* A, const __nv_bfloat16* Bt,
    int m0, int n0, int tid)
{
    const char* aSrc = (const char*)(A  + (size_t)m0 * KPP_ + ktile * 64);
    const char* bSrc = (const char*)(Bt + (size_t)n0 * KPP_ + ktile * 64);
    const uint32_t sa = sbase + stage * 32768;
    const uint32_t sbB = sa + 16384;
#pragma unroll
    for (int i = 0; i < 8; i++) {
        const int u = i * 128 + tid;
        const int r = u >> 3, c = u & 7;
        cp_async16(sa + r * 128 + ((c ^ (r & 7)) << 4),
                   aSrc + (size_t)r * (KPP_ * 2) + c * 16);
    }
#pragma unroll
    for (int i = 0; i < 8; i++) {
        const int u = i * 128 + tid;
        const int r = u >> 3, c = u & 7;
        cp_async16(sbB + r * 128 + ((c ^ (r & 7)) << 4),
                   bSrc + (size_t)r * (KPP_ * 2) + c * 16);
    }
    cp_commit();
}

__global__ __launch_bounds__(128) void hmma_gemm_kernel(
    const float* __restrict__ bias, float* __restrict__ out, int mode)
{
    extern __shared__ char smem[];
    const uint32_t sb = smem_u32(smem);

    const __nv_bfloat16* A  = g_at;
    const __nv_bfloat16* Bt = (mode == 0) ? g_wqt : g_wpt;

    const int tid  = threadIdx.x;
    const int lane = tid & 31, wid = tid >> 5;
    const int warp_m = wid & 1, warp_n = wid >> 1;
    const int m0 = blockIdx.y * 128, n0 = blockIdx.x * 128;

    float acc[4][8][4];
#pragma unroll
    for (int i = 0; i < 4; i++)
#pragma unroll
        for (int j = 0; j < 8; j++)
#pragma unroll
            for (int r = 0; r < 4; r++) acc[i][j][r] = 0.f;

    load_tile(sb, 0, 0, A, Bt, m0, n0, tid);
    load_tile(sb, 1, 1, A, Bt, m0, n0, tid);

    const int lane15 = lane & 15, lhalf = lane >> 4;
    const int ra  = warp_m * 64 + lane15;   // A fragment base row (+16*mi)
    const int rbw = warp_n * 64 + lane15;   // B fragment base row (+16*ng)

    for (int kt = 0; kt < KT_; kt++) {
        asm volatile("cp.async.wait_group 1;" ::: "memory");
        __syncthreads();   // data-ready for kt AND safe reuse of stage (kt+2)%3
        if (kt + 2 < KT_)
            load_tile(sb, (kt + 2) % 3, kt + 2, A, Bt, m0, n0, tid);
        else
            cp_commit();   // keep group counting uniform

        const uint32_t sa  = sb + (kt % 3) * 32768;
        const uint32_t sbB = sa + 16384;

        uint32_t afr[2][4][4], bfr[2][4][4];
        // prefetch k-chunk 0 into buffer 0
        {
            const int kc = lhalf;
#pragma unroll
            for (int mi = 0; mi < 4; mi++) {
                const int r = ra + mi * 16;
                ldmatrix_x4(afr[0][mi], sa + r * 128 + ((kc ^ (r & 7)) << 4));
            }
#pragma unroll
            for (int ng = 0; ng < 4; ng++) {
                const int r = rbw + ng * 16;
                ldmatrix_x4(bfr[0][ng], sbB + r * 128 + ((kc ^ (r & 7)) << 4));
            }
        }
#pragma unroll
        for (int kk = 0; kk < 4; kk++) {
            const int cur = kk & 1, nxt = cur ^ 1;
            if (kk < 3) {   // prefetch next k-chunk into alternate buffer
                const int kc = (kk + 1) * 2 + lhalf;
#pragma unroll
                for (int mi = 0; mi < 4; mi++) {
                    const int r = ra + mi * 16;
                    ldmatrix_x4(afr[nxt][mi], sa + r * 128 + ((kc ^ (r & 7)) << 4));
                }
#pragma unroll
                for (int ng = 0; ng < 4; ng++) {
                    const int r = rbw + ng * 16;
                    ldmatrix_x4(bfr[nxt][ng], sbB + r * 128 + ((kc ^ (r & 7)) << 4));
                }
            }
#pragma unroll
            for (int mi = 0; mi < 4; mi++)
#pragma unroll
                for (int nj = 0; nj < 8; nj++)
                    mma16816(acc[mi][nj], afr[cur][mi],
                             bfr[cur][nj >> 1][nj & 1],
                             bfr[cur][nj >> 1][(nj & 1) + 2]);
        }
    }

    // Epilogue
    const int mrow = m0 + warp_m * 64 + (lane >> 2);
    const int ncb  = n0 + warp_n * 64 + (lane & 3) * 2;
#pragma unroll
    for (int mi = 0; mi < 4; mi++) {
#pragma unroll
        for (int nj = 0; nj < 8; nj++) {
            const int c  = ncb + nj * 8;
            const float b0 = bias[c], b1 = bias[c + 1];
            const int r0 = mrow + mi * 16;
            float v00 = acc[mi][nj][0] + b0, v01 = acc[mi][nj][1] + b1;
            float v10 = acc[mi][nj][2] + b0, v11 = acc[mi][nj][3] + b1;
            if (mode == 1) {
                float2 p0; p0.x = v00; p0.y = v01;
                float2 p1; p1.x = v10; p1.y = v11;
                *(float2*)&out[(size_t)r0 * E_ + c] = p0;
                *(float2*)&out[(size_t)(r0 + 8) * E_ + c] = p1;
                continue;
            }
            __nv_bfloat16 h00, l00, h01, l01, h10, l10, h11, l11;
            split_bf(v00, h00, l00); split_bf(v01, h01, l01);
            split_bf(v10, h10, l10); split_bf(v11, h11, l11);
            const int sec = c >> 10, e = c & 1023;
            const int hh = e >> 6, dd = e & 63;
            const int bb = r0 >> 10, nn = r0 & 1023;
            if (sec <= 1) {
                __nv_bfloat16* dh = sec == 0 ? g_qh : g_kh;
                __nv_bfloat16* dl = sec == 0 ? g_ql : g_kl;
                const size_t i0 = (((size_t)bb * H_ + hh) * N_ + nn) * D_ + dd;
                const size_t i1 = i0 + 8 * D_;
                *(uint32_t*)&dh[i0] = packbf2(h00, h01);
                *(uint32_t*)&dl[i0] = packbf2(l00, l01);
                *(uint32_t*)&dh[i1] = packbf2(h10, h11);
                *(uint32_t*)&dl[i1] = packbf2(l10, l11);
            } else {
                const size_t i00 = (((size_t)bb * H_ + hh) * D_ + dd) * N_ + nn;
                g_vth[i00] = h00;          g_vtl[i00] = l00;
                g_vth[i00 + N_] = h01;     g_vtl[i00 + N_] = l01;
                g_vth[i00 + 8] = h10;      g_vtl[i00 + 8] = l10;
                g_vth[i00 + N_ + 8] = h11; g_vtl[i00 + N_ + 8] = l11;
            }
        }
    }
}

// ---------------------------------------------------------------------------
// Flash attention on HMMA. 3-stage pipeline, ONE barrier per kv-iter.
// ---------------------------------------------------------------------------
#define ATT_SMEM (3 * 32768)
// stage layout: Kh @0, Kl @8192, Vh @16384, Vl @24576 (each 64 rows x 128B)

__device__ __forceinline__ void att_load_tile(
    uint32_t st, int kv0,
    const __nv_bfloat16* kh, const __nv_bfloat16* kl,
    const __nv_bfloat16* vh, const __nv_bfloat16* vl, int tid)
{
#pragma unroll
    for (int i = 0; i < 4; i++) {
        const int u = i * 128 + tid;
        const int r = u >> 3, c = u & 7;
        const uint32_t soff = r * 128 + ((c ^ (r & 7)) << 4);
        cp_async16(st + soff,         (const char*)kh + (size_t)(kv0 + r) * 128 + c * 16);
        cp_async16(st + 8192 + soff,  (const char*)kl + (size_t)(kv0 + r) * 128 + c * 16);
        cp_async16(st + 16384 + soff, (const char*)vh + (size_t)r * 2048 + kv0 * 2 + c * 16);
        cp_async16(st + 24576 + soff, (const char*)vl + (size_t)r * 2048 + kv0 * 2 + c * 16);
    }
    cp_commit();
}

__global__ __launch_bounds__(128) void attn_hmma_kernel()
{
    extern __shared__ char smem[];
    const uint32_t sb = smem_u32(smem);

    const int tid = threadIdx.x;
    const int lane = tid & 31, w = tid >> 5;
    const int lane15 = lane & 15, lhalf = lane >> 4;
    const int q0 = blockIdx.x * 64;
    const int h  = blockIdx.y;
    const int b  = blockIdx.z;

    const size_t hb = (size_t)(b * H_ + h) * (N_ * D_);
    const __nv_bfloat16* qh = g_qh + hb;
    const __nv_bfloat16* ql = g_ql + hb;
    const __nv_bfloat16* kh = g_kh + hb;
    const __nv_bfloat16* kl = g_kl + hb;
    const __nv_bfloat16* vh = g_vth + hb;
    const __nv_bfloat16* vl = g_vtl + hb;

    // stage Q in stage-0 area, extract fragments
#pragma unroll
    for (int i = 0; i < 4; i++) {
        const int u = i * 128 + tid;
        const int r = u >> 3, c = u & 7;
        const uint32_t soff = r * 128 + ((c ^ (r & 7)) << 4);
        cp_async16(sb + soff,        (const char*)qh + (size_t)(q0 + r) * 128 + c * 16);
        cp_async16(sb + 8192 + soff, (const char*)ql + (size_t)(q0 + r) * 128 + c * 16);
    }
    cp_commit();
    asm volatile("cp.async.wait_group 0;" ::: "memory");
    __syncthreads();

    uint32_t qfh[4][4], qfl[4][4];
    {
        const int r = w * 16 + lane15;
#pragma unroll
        for (int t = 0; t < 4; t++) {
            const uint32_t soff = r * 128 + (((t * 2 + lhalf) ^ (r & 7)) << 4);
            ldmatrix_x4(qfh[t], sb + soff);
            ldmatrix_x4(qfl[t], sb + 8192 + soff);
        }
    }
    __syncthreads();

    float mstate[2] = {-1e30f, -1e30f};
    float lstate[2] = {0.f, 0.f};
    float oacc[8][4];
#pragma unroll
    for (int j = 0; j < 8; j++)
#pragma unroll
        for (int r = 0; r < 4; r++) oacc[j][r] = 0.f;

    const float cexp = 0.18033688f;   // D^-0.5 * log2(e)

    att_load_tile(sb, 0, kh, kl, vh, vl, tid);
    att_load_tile(sb + 32768, 64, kh, kl, vh, vl, tid);

    for (int t = 0; t < 16; t++) {
        asm volatile("cp.async.wait_group 1;" ::: "memory");
        __syncthreads();   // data-ready for t AND safe reuse of stage (t+2)%3
        if (t + 2 < 16)
            att_load_tile(sb + ((t + 2) % 3) * 32768, (t + 2) * 64, kh, kl, vh, vl, tid);
        else
            cp_commit();

        const uint32_t stK = sb + (t % 3) * 32768;
        const uint32_t stV = stK + 16384;

        float sacc[8][4];
#pragma unroll
        for (int j = 0; j < 8; j++)
#pragma unroll
            for (int r = 0; r < 4; r++) sacc[j][r] = 0.f;

#pragma unroll
        for (int kvg = 0; kvg < 4; kvg++) {
            const int rb = kvg * 16 + lane15;
#pragma unroll
            for (int kk = 0; kk < 4; kk++) {
                const uint32_t soff = rb * 128 + (((kk * 2 + lhalf) ^ (rb & 7)) << 4);
                uint32_t bf[4];
                ldmatrix_x4(bf, stK + soff);
                mma16816(sacc[2 * kvg],     qfh[kk], bf[0], bf[2]);
                mma16816(sacc[2 * kvg + 1], qfh[kk], bf[1], bf[3]);
                mma16816(sacc[2 * kvg],     qfl[kk], bf[0], bf[2]);
                mma16816(sacc[2 * kvg + 1], qfl[kk], bf[1], bf[3]);
                ldmatrix_x4(bf, stK + 8192 + soff);
                mma16816(sacc[2 * kvg],     qfh[kk], bf[0], bf[2]);
                mma16816(sacc[2 * kvg + 1], qfh[kk], bf[1], bf[3]);
            }
        }

#pragma unroll
        for (int rr = 0; rr < 2; rr++) {
            float mx = -1e30f;
#pragma unroll
            for (int j = 0; j < 8; j++)
                mx = fmaxf(mx, fmaxf(sacc[j][rr * 2], sacc[j][rr * 2 + 1]));
            mx = fmaxf(mx, __shfl_xor_sync(0xffffffffu, mx, 1));
            mx = fmaxf(mx, __shfl_xor_sync(0xffffffffu, mx, 2));
            const float mnew  = fmaxf(mstate[rr], mx);
            const float alpha = exp2f((mstate[rr] - mnew) * cexp);
            mstate[rr] = mnew;
            float rs = 0.f;
#pragma unroll
            for (int j = 0; j < 8; j++) {
                const float p0 = exp2f((sacc[j][rr * 2]     - mnew) * cexp);
                const float p1 = exp2f((sacc[j][rr * 2 + 1] - mnew) * cexp);
                sacc[j][rr * 2] = p0; sacc[j][rr * 2 + 1] = p1;
                rs += p0 + p1;
            }
            rs += __shfl_xor_sync(0xffffffffu, rs, 1);
            rs += __shfl_xor_sync(0xffffffffu, rs, 2);
            lstate[rr] = lstate[rr] * alpha + rs;
#pragma unroll
            for (int j = 0; j < 8; j++) {
                oacc[j][rr * 2]     *= alpha;
                oacc[j][rr * 2 + 1] *= alpha;
            }
        }

        uint32_t ph[4][4], pl[4][4];
#pragma unroll
        for (int kk = 0; kk < 4; kk++) {
#pragma unroll
            for (int q = 0; q < 4; q++) {
                const int tile = 2 * kk + (q >> 1);
                const int ri   = (q & 1) * 2;
                const float p0 = sacc[tile][ri], p1 = sacc[tile][ri + 1];
                __nv_bfloat16 h0, l0, h1, l1;
                split_bf(p0, h0, l0); split_bf(p1, h1, l1);
                ph[kk][q] = packbf2(h0, h1);
                pl[kk][q] = packbf2(l0, l1);
            }
        }

#pragma unroll
        for (int dg = 0; dg < 4; dg++) {
            const int rb = dg * 16 + lane15;
#pragma unroll
            for (int kk = 0; kk < 4; kk++) {
                const uint32_t soff = rb * 128 + (((kk * 2 + lhalf) ^ (rb & 7)) << 4);
                uint32_t bf[4];
                ldmatrix_x4(bf, stV + soff);
                mma16816(oacc[2 * dg],     ph[kk], bf[0], bf[2]);
                mma16816(oacc[2 * dg + 1], ph[kk], bf[1], bf[3]);
                mma16816(oacc[2 * dg],     pl[kk], bf[0], bf[2]);
                mma16816(oacc[2 * dg + 1], pl[kk], bf[1], bf[3]);
                ldmatrix_x4(bf, stV + 8192 + soff);
                mma16816(oacc[2 * dg],     ph[kk], bf[0], bf[2]);
                mma16816(oacc[2 * dg + 1], ph[kk], bf[1], bf[3]);
            }
        }
    }

    const float inv0 = 1.f / lstate[0];
    const float inv1 = 1.f / lstate[1];
    const int qrow = q0 + w * 16 + (lane >> 2);
    const size_t m0r = (size_t)(b * N_ + qrow) * KPP_;
    const size_t m1r = m0r + (size_t)8 * KPP_;
    const int colb = h * 64 + 2 * (lane & 3);
#pragma unroll
    for (int j = 0; j < 8; j++) {
        const int col = colb + 8 * j;
        {
            __nv_bfloat16 h0, l0, h1, l1;
            split_bf(oacc[j][0] * inv0, h0, l0);
            split_bf(oacc[j][1] * inv0, h1, l1);
            const uint32_t hi = packbf2(h0, h1), lo = packbf2(l0, l1);
            *(uint32_t*)&g_at[m0r + col]        = hi;
            *(uint32_t*)&g_at[m0r + 1024 + col] = lo;
            *(uint32_t*)&g_at[m0r + 2048 + col] = hi;
        }
        {
            __nv_bfloat16 h0, l0, h1, l1;
            split_bf(oacc[j][2] * inv1, h0, l0);
            split_bf(oacc[j][3] * inv1, h1, l1);
            const uint32_t hi = packbf2(h0, h1), lo = packbf2(l0, l1);
            *(uint32_t*)&g_at[m1r + col]        = hi;
            *(uint32_t*)&g_at[m1r + 1024 + col] = lo;
            *(uint32_t*)&g_at[m1r + 2048 + col] = hi;
        }
    }
}

// ---------------------------------------------------------------------------
extern "C" void kernel_launch(void* const* d_in, const int* in_sizes, int n_in,
                              void* d_out, int out_size)
{
    const float* x  = (const float*)d_in[0];
    const float* Wq = (const float*)d_in[1];
    const float* bq = (const float*)d_in[2];
    const float* Wp = (const float*)d_in[3];
    const float* bp = (const float*)d_in[4];
    float* out = (float*)d_out;

    cudaFuncSetAttribute(hmma_gemm_kernel,
                         cudaFuncAttributeMaxDynamicSharedMemorySize, GEMM_SMEM);
    cudaFuncSetAttribute(attn_hmma_kernel,
                         cudaFuncAttributeMaxDynamicSharedMemorySize, ATT_SMEM);

    conv_a_kernel<<<M_, 256>>>(x);
    conv_w_kernel<<<QKV_N, 256>>>(Wq, QKV_N, 0);
    conv_w_kernel<<<E_, 256>>>(Wp, E_, 1);

    hmma_gemm_kernel<<<dim3(QKV_N / 128, M_ / 128), 128, GEMM_SMEM>>>(bq, out, 0);

    attn_hmma_kernel<<<dim3(N_ / 64, H_, B_), 128, ATT_SMEM>>>();

    hmma_gemm_kernel<<<dim3(E_ / 128, M_ / 128), 128, GEMM_SMEM>>>(bp, out, 1);
}

// round 8
// speedup vs baseline: 2.7078x; 2.7057x over previous
#include <cuda_runtime.h>
#include <cuda_fp16.h>
#include <cstdint>

#define B_   16
#define N_   1024
#define E_   1024
#define H_   16
#define D_   64
#define M_   (B_ * N_)        // 16384
#define QKV_N (3 * E_)        // 3072
#define KT_   (E_ / 64)       // 16 k-iters of 64

// ---------------------------------------------------------------------------
// Scratch (__device__ globals; no allocations)
// ---------------------------------------------------------------------------
static __device__ __align__(1024) __half g_q16 [(size_t)B_ * H_ * N_ * D_];
static __device__ __align__(1024) __half g_k16 [(size_t)B_ * H_ * N_ * D_];
static __device__ __align__(1024) __half g_vt16[(size_t)B_ * H_ * D_ * N_];  // V^T [B,H,D,N]
static __device__ __align__(1024) __half g_a16 [(size_t)M_ * E_];   // x, then attn out
static __device__ __align__(1024) __half g_wq16[(size_t)QKV_N * E_];  // Wqkv^T (n-major)
static __device__ __align__(1024) __half g_wp16[(size_t)E_ * E_];     // Wproj^T (n-major)

// ---------------------------------------------------------------------------
// helpers
// ---------------------------------------------------------------------------
__device__ __forceinline__ uint32_t smem_u32(const void* p) {
    uint32_t a;
    asm("{ .reg .u64 t; cvta.to.shared.u64 t, %1; cvt.u32.u64 %0, t; }"
        : "=r"(a) : "l"(p));
    return a;
}
__device__ __forceinline__ void cp_async16(uint32_t dst, const void* src) {
    asm volatile("cp.async.cg.shared.global [%0], [%1], 16;" :: "r"(dst), "l"(src));
}
__device__ __forceinline__ void cp_commit() {
    asm volatile("cp.async.commit_group;" ::: "memory");
}
__device__ __forceinline__ void ldmatrix_x4(uint32_t* d, uint32_t addr) {
    asm volatile("ldmatrix.sync.aligned.m8n8.x4.shared.b16 {%0,%1,%2,%3}, [%4];"
                 : "=r"(d[0]), "=r"(d[1]), "=r"(d[2]), "=r"(d[3]) : "r"(addr));
}
__device__ __forceinline__ void mma16816(float* c, const uint32_t* a,
                                         uint32_t b0, uint32_t b1) {
    asm volatile(
        "mma.sync.aligned.m16n8k16.row.col.f32.f16.f16.f32 "
        "{%0,%1,%2,%3}, {%4,%5,%6,%7}, {%8,%9}, {%0,%1,%2,%3};"
        : "+f"(c[0]), "+f"(c[1]), "+f"(c[2]), "+f"(c[3])
        : "r"(a[0]), "r"(a[1]), "r"(a[2]), "r"(a[3]), "r"(b0), "r"(b1));
}
__device__ __forceinline__ uint32_t packh2(float x, float y) {
    __half2 h = __floats2half2_rn(x, y);
    return *reinterpret_cast<uint32_t*>(&h);
}

// ---------------------------------------------------------------------------
// conv_a: fp32 [M,1024] -> fp16 row-major g_a16
// ---------------------------------------------------------------------------
__global__ __launch_bounds__(256) void conv_a_kernel(const float* __restrict__ src)
{
    const int m  = blockIdx.x;
    const int k4 = threadIdx.x << 2;
    float4 v = *(const float4*)(src + (size_t)m * E_ + k4);
    uint2 o;
    o.x = packh2(v.x, v.y);
    o.y = packh2(v.z, v.w);
    *(uint2*)&g_a16[(size_t)m * E_ + k4] = o;
}

// ---------------------------------------------------------------------------
// conv_w: W [1024][Ncols] fp32 -> W^T fp16 (row n, k contiguous)
// ---------------------------------------------------------------------------
__global__ __launch_bounds__(256) void conv_w_kernel(
    const float* __restrict__ W, int Ncols, int which)
{
    __half* dst = which ? g_wp16 : g_wq16;
    const int n  = blockIdx.x;
    const int k4 = threadIdx.x << 2;
    float f[4];
#pragma unroll
    for (int j = 0; j < 4; j++) f[j] = W[(size_t)(k4 + j) * Ncols + n];
    uint2 o;
    o.x = packh2(f[0], f[1]);
    o.y = packh2(f[2], f[3]);
    *(uint2*)&dst[(size_t)n * E_ + k4] = o;
}

// ---------------------------------------------------------------------------
// fp16 HMMA GEMM: C[M,Ncols] = A[M,1024] @ W^T + bias. CTA 128x128, 4 warps
// (warp tile 64x64), 3-stage cp.async, 1 barrier/k-iter, reg-dbuf fragments.
// mode 0: write Q/K fp16 [B,H,N,D] + V^T fp16 [B,H,D,N]; mode 1: fp32 out.
// ---------------------------------------------------------------------------
#define GEMM_SMEM (3 * 32768)

__device__ __forceinline__ void load_tile(
    uint32_t sbase, int stage, int ktile,
    const __half* A, const __half* Bt, int m0, int n0, int tid)
{
    const char* aSrc = (const char*)(A  + (size_t)m0 * E_ + ktile * 64);
    const char* bSrc = (const char*)(Bt + (size_t)n0 * E_ + ktile * 64);
    const uint32_t sa  = sbase + stage * 32768;
    const uint32_t sbB = sa + 16384;
#pragma unroll
    for (int i = 0; i < 8; i++) {
        const int u = i * 128 + tid;
        const int r = u >> 3, c = u & 7;
        cp_async16(sa + r * 128 + ((c ^ (r & 7)) << 4),
                   aSrc + (size_t)r * (E_ * 2) + c * 16);
    }
#pragma unroll
    for (int i = 0; i < 8; i++) {
        const int u = i * 128 + tid;
        const int r = u >> 3, c = u & 7;
        cp_async16(sbB + r * 128 + ((c ^ (r & 7)) << 4),
                   bSrc + (size_t)r * (E_ * 2) + c * 16);
    }
    cp_commit();
}

__global__ __launch_bounds__(128) void hgemm_kernel(
    const float* __restrict__ bias, float* __restrict__ out, int mode)
{
    extern __shared__ char smem[];
    const uint32_t sb = smem_u32(smem);
    const __half* A  = g_a16;
    const __half* Bt = (mode == 0) ? g_wq16 : g_wp16;

    const int tid  = threadIdx.x;
    const int lane = tid & 31, wid = tid >> 5;
    const int warp_m = wid & 1, warp_n = wid >> 1;
    const int m0 = blockIdx.y * 128, n0 = blockIdx.x * 128;

    float acc[4][8][4];
#pragma unroll
    for (int i = 0; i < 4; i++)
#pragma unroll
        for (int j = 0; j < 8; j++)
#pragma unroll
            for (int r = 0; r < 4; r++) acc[i][j][r] = 0.f;

    load_tile(sb, 0, 0, A, Bt, m0, n0, tid);
    load_tile(sb, 1, 1, A, Bt, m0, n0, tid);

    const int lane15 = lane & 15, lhalf = lane >> 4;
    const int ra  = warp_m * 64 + lane15;
    const int rbw = warp_n * 64 + lane15;

    for (int kt = 0; kt < KT_; kt++) {
        asm volatile("cp.async.wait_group 1;" ::: "memory");
        __syncthreads();
        if (kt + 2 < KT_)
            load_tile(sb, (kt + 2) % 3, kt + 2, A, Bt, m0, n0, tid);
        else
            cp_commit();

        const uint32_t sa  = sb + (kt % 3) * 32768;
        const uint32_t sbB = sa + 16384;

        uint32_t afr[2][4][4], bfr[2][4][4];
        {
            const int kc = lhalf;
#pragma unroll
            for (int mi = 0; mi < 4; mi++) {
                const int r = ra + mi * 16;
                ldmatrix_x4(afr[0][mi], sa + r * 128 + ((kc ^ (r & 7)) << 4));
            }
#pragma unroll
            for (int ng = 0; ng < 4; ng++) {
                const int r = rbw + ng * 16;
                ldmatrix_x4(bfr[0][ng], sbB + r * 128 + ((kc ^ (r & 7)) << 4));
            }
        }
#pragma unroll
        for (int kk = 0; kk < 4; kk++) {
            const int cur = kk & 1, nxt = cur ^ 1;
            if (kk < 3) {
                const int kc = (kk + 1) * 2 + lhalf;
#pragma unroll
                for (int mi = 0; mi < 4; mi++) {
                    const int r = ra + mi * 16;
                    ldmatrix_x4(afr[nxt][mi], sa + r * 128 + ((kc ^ (r & 7)) << 4));
                }
#pragma unroll
                for (int ng = 0; ng < 4; ng++) {
                    const int r = rbw + ng * 16;
                    ldmatrix_x4(bfr[nxt][ng], sbB + r * 128 + ((kc ^ (r & 7)) << 4));
                }
            }
#pragma unroll
            for (int mi = 0; mi < 4; mi++)
#pragma unroll
                for (int nj = 0; nj < 8; nj++)
                    mma16816(acc[mi][nj], afr[cur][mi],
                             bfr[cur][nj >> 1][nj & 1],
                             bfr[cur][nj >> 1][(nj & 1) + 2]);
        }
    }

    const int mrow = m0 + warp_m * 64 + (lane >> 2);
    const int ncb  = n0 + warp_n * 64 + (lane & 3) * 2;
#pragma unroll
    for (int mi = 0; mi < 4; mi++) {
#pragma unroll
        for (int nj = 0; nj < 8; nj++) {
            const int c  = ncb + nj * 8;
            const float b0 = bias[c], b1 = bias[c + 1];
            const int r0 = mrow + mi * 16;
            const float v00 = acc[mi][nj][0] + b0, v01 = acc[mi][nj][1] + b1;
            const float v10 = acc[mi][nj][2] + b0, v11 = acc[mi][nj][3] + b1;
            if (mode == 1) {
                float2 p0; p0.x = v00; p0.y = v01;
                float2 p1; p1.x = v10; p1.y = v11;
                *(float2*)&out[(size_t)r0 * E_ + c] = p0;
                *(float2*)&out[(size_t)(r0 + 8) * E_ + c] = p1;
                continue;
            }
            const int sec = c >> 10, e = c & 1023;
            const int hh = e >> 6, dd = e & 63;
            const int bb = r0 >> 10, nn = r0 & 1023;
            if (sec <= 1) {
                __half* dq = sec == 0 ? g_q16 : g_k16;
                const size_t i0 = (((size_t)bb * H_ + hh) * N_ + nn) * D_ + dd;
                *(uint32_t*)&dq[i0]          = packh2(v00, v01);
                *(uint32_t*)&dq[i0 + 8 * D_] = packh2(v10, v11);
            } else {
                const size_t i00 = (((size_t)bb * H_ + hh) * D_ + dd) * N_ + nn;
                g_vt16[i00]          = __float2half_rn(v00);
                g_vt16[i00 + N_]     = __float2half_rn(v01);
                g_vt16[i00 + 8]      = __float2half_rn(v10);
                g_vt16[i00 + N_ + 8] = __float2half_rn(v11);
            }
        }
    }
}

// ---------------------------------------------------------------------------
// Flash attention, fp16 single-term HMMA. 2-stage pipeline (R5 structure).
// stage: K @0 (8KB), V^T @8192 (8KB); stride 16384; total 32KB.
// ---------------------------------------------------------------------------
#define ATT_SMEM (2 * 16384)

__device__ __forceinline__ void att_load_tile(
    uint32_t st, int kv0, const __half* k16, const __half* vt16, int tid)
{
#pragma unroll
    for (int i = 0; i < 4; i++) {
        const int u = i * 128 + tid;
        const int r = u >> 3, c = u & 7;
        const uint32_t soff = r * 128 + ((c ^ (r & 7)) << 4);
        cp_async16(st + soff,        (const char*)k16  + (size_t)(kv0 + r) * 128 + c * 16);
        cp_async16(st + 8192 + soff, (const char*)vt16 + (size_t)r * 2048 + kv0 * 2 + c * 16);
    }
    cp_commit();
}

__global__ __launch_bounds__(128) void attn_kernel()
{
    extern __shared__ char smem[];
    const uint32_t sb = smem_u32(smem);

    const int tid = threadIdx.x;
    const int lane = tid & 31, w = tid >> 5;
    const int lane15 = lane & 15, lhalf = lane >> 4;
    const int q0 = blockIdx.x * 64;
    const int h  = blockIdx.y;
    const int b  = blockIdx.z;

    const size_t hb = (size_t)(b * H_ + h) * (N_ * D_);
    const __half* q16  = g_q16  + hb;
    const __half* k16  = g_k16  + hb;
    const __half* vt16 = g_vt16 + hb;

    // stage Q in stage-0 K region, extract fragments
#pragma unroll
    for (int i = 0; i < 4; i++) {
        const int u = i * 128 + tid;
        const int r = u >> 3, c = u & 7;
        cp_async16(sb + r * 128 + ((c ^ (r & 7)) << 4),
                   (const char*)q16 + (size_t)(q0 + r) * 128 + c * 16);
    }
    cp_commit();
    asm volatile("cp.async.wait_group 0;" ::: "memory");
    __syncthreads();

    uint32_t qf[4][4];
    {
        const int r = w * 16 + lane15;
#pragma unroll
        for (int t = 0; t < 4; t++)
            ldmatrix_x4(qf[t], sb + r * 128 + (((t * 2 + lhalf) ^ (r & 7)) << 4));
    }
    __syncthreads();

    float mstate[2] = {-1e30f, -1e30f};
    float lstate[2] = {0.f, 0.f};
    float oacc[8][4];
#pragma unroll
    for (int j = 0; j < 8; j++)
#pragma unroll
        for (int r = 0; r < 4; r++) oacc[j][r] = 0.f;

    const float cexp = 0.18033688f;   // D^-0.5 * log2(e)

    att_load_tile(sb, 0, k16, vt16, tid);
    att_load_tile(sb + 16384, 64, k16, vt16, tid);

    for (int t = 0; t < 16; t++) {
        asm volatile("cp.async.wait_group 1;" ::: "memory");
        __syncthreads();
        const uint32_t stK = sb + (t & 1) * 16384;
        const uint32_t stV = stK + 8192;

        float sacc[8][4];
#pragma unroll
        for (int j = 0; j < 8; j++)
#pragma unroll
            for (int r = 0; r < 4; r++) sacc[j][r] = 0.f;

#pragma unroll
        for (int kvg = 0; kvg < 4; kvg++) {
            const int rb = kvg * 16 + lane15;
#pragma unroll
            for (int kk = 0; kk < 4; kk++) {
                uint32_t bf[4];
                ldmatrix_x4(bf, stK + rb * 128 + (((kk * 2 + lhalf) ^ (rb & 7)) << 4));
                mma16816(sacc[2 * kvg],     qf[kk], bf[0], bf[2]);
                mma16816(sacc[2 * kvg + 1], qf[kk], bf[1], bf[3]);
            }
        }

#pragma unroll
        for (int rr = 0; rr < 2; rr++) {
            float mx = -1e30f;
#pragma unroll
            for (int j = 0; j < 8; j++)
                mx = fmaxf(mx, fmaxf(sacc[j][rr * 2], sacc[j][rr * 2 + 1]));
            mx = fmaxf(mx, __shfl_xor_sync(0xffffffffu, mx, 1));
            mx = fmaxf(mx, __shfl_xor_sync(0xffffffffu, mx, 2));
            const float mnew  = fmaxf(mstate[rr], mx);
            const float alpha = exp2f((mstate[rr] - mnew) * cexp);
            mstate[rr] = mnew;
            float rs = 0.f;
#pragma unroll
            for (int j = 0; j < 8; j++) {
                const float p0 = exp2f((sacc[j][rr * 2]     - mnew) * cexp);
                const float p1 = exp2f((sacc[j][rr * 2 + 1] - mnew) * cexp);
                sacc[j][rr * 2] = p0; sacc[j][rr * 2 + 1] = p1;
                rs += p0 + p1;
            }
            rs += __shfl_xor_sync(0xffffffffu, rs, 1);
            rs += __shfl_xor_sync(0xffffffffu, rs, 2);
            lstate[rr] = lstate[rr] * alpha + rs;
#pragma unroll
            for (int j = 0; j < 8; j++) {
                oacc[j][rr * 2]     *= alpha;
                oacc[j][rr * 2 + 1] *= alpha;
            }
        }

        // P fragments in registers (C-frag layout == A-frag layout)
        uint32_t pf[4][4];
#pragma unroll
        for (int kk = 0; kk < 4; kk++) {
#pragma unroll
            for (int q = 0; q < 4; q++) {
                const int tile = 2 * kk + (q >> 1);
                const int ri   = (q & 1) * 2;
                pf[kk][q] = packh2(sacc[tile][ri], sacc[tile][ri + 1]);
            }
        }

#pragma unroll
        for (int dg = 0; dg < 4; dg++) {
            const int rb = dg * 16 + lane15;
#pragma unroll
            for (int kk = 0; kk < 4; kk++) {
                uint32_t bf[4];
                ldmatrix_x4(bf, stV + rb * 128 + (((kk * 2 + lhalf) ^ (rb & 7)) << 4));
                mma16816(oacc[2 * dg],     pf[kk], bf[0], bf[2]);
                mma16816(oacc[2 * dg + 1], pf[kk], bf[1], bf[3]);
            }
        }

        __syncthreads();
        if (t + 2 < 16)
            att_load_tile(sb + (t & 1) * 16384, (t + 2) * 64, k16, vt16, tid);
        else
            cp_commit();
    }

    // epilogue: normalize, write fp16 O rows into g_a16 [M, E]
    const float inv0 = 1.f / lstate[0];
    const float inv1 = 1.f / lstate[1];
    const int qrow = q0 + w * 16 + (lane >> 2);
    const size_t m0r = (size_t)(b * N_ + qrow) * E_;
    const size_t m1r = m0r + (size_t)8 * E_;
    const int colb = h * 64 + 2 * (lane & 3);
#pragma unroll
    for (int j = 0; j < 8; j++) {
        const int col = colb + 8 * j;
        *(uint32_t*)&g_a16[m0r + col] = packh2(oacc[j][0] * inv0, oacc[j][1] * inv0);
        *(uint32_t*)&g_a16[m1r + col] = packh2(oacc[j][2] * inv1, oacc[j][3] * inv1);
    }
}

// ---------------------------------------------------------------------------
extern "C" void kernel_launch(void* const* d_in, const int* in_sizes, int n_in,
                              void* d_out, int out_size)
{
    const float* x  = (const float*)d_in[0];
    const float* Wq = (const float*)d_in[1];
    const float* bq = (const float*)d_in[2];
    const float* Wp = (const float*)d_in[3];
    const float* bp = (const float*)d_in[4];
    float* out = (float*)d_out;

    cudaFuncSetAttribute(hgemm_kernel,
                         cudaFuncAttributeMaxDynamicSharedMemorySize, GEMM_SMEM);
    cudaFuncSetAttribute(attn_kernel,
                         cudaFuncAttributeMaxDynamicSharedMemorySize, ATT_SMEM);

    conv_a_kernel<<<M_, 256>>>(x);
    conv_w_kernel<<<QKV_N, 256>>>(Wq, QKV_N, 0);
    conv_w_kernel<<<E_, 256>>>(Wp, E_, 1);

    hgemm_kernel<<<dim3(QKV_N / 128, M_ / 128), 128, GEMM_SMEM>>>(bq, out, 0);

    attn_kernel<<<dim3(N_ / 64, H_, B_), 128, ATT_SMEM>>>();

    hgemm_kernel<<<dim3(E_ / 128, M_ / 128), 128, GEMM_SMEM>>>(bp, out, 1);
}

// round 9
// speedup vs baseline: 2.7149x; 1.0026x over previous
#include <cuda_runtime.h>
#include <cuda_fp16.h>
#include <cstdint>

#define B_   16
#define N_   1024
#define E_   1024
#define H_   16
#define D_   64
#define M_   (B_ * N_)        // 16384
#define QKV_N (3 * E_)        // 3072
#define KT_   (E_ / 64)       // 16 k-iters of 64

// ---------------------------------------------------------------------------
// Scratch (__device__ globals; no allocations)
// ---------------------------------------------------------------------------
static __device__ __align__(1024) __half g_q16 [(size_t)B_ * H_ * N_ * D_];
static __device__ __align__(1024) __half g_k16 [(size_t)B_ * H_ * N_ * D_];
static __device__ __align__(1024) __half g_vt16[(size_t)B_ * H_ * D_ * N_];  // V^T [B,H,D,N]
static __device__ __align__(1024) __half g_a16 [(size_t)M_ * E_];    // x, then attn out
static __device__ __align__(1024) __half g_wq16[(size_t)QKV_N * E_]; // Wqkv^T (n-major)
static __device__ __align__(1024) __half g_wp16[(size_t)E_ * E_];    // Wproj^T (n-major)

// ---------------------------------------------------------------------------
// helpers
// ---------------------------------------------------------------------------
__device__ __forceinline__ uint32_t smem_u32(const void* p) {
    uint32_t a;
    asm("{ .reg .u64 t; cvta.to.shared.u64 t, %1; cvt.u32.u64 %0, t; }"
        : "=r"(a) : "l"(p));
    return a;
}
__device__ __forceinline__ void cp_async16(uint32_t dst, const void* src) {
    asm volatile("cp.async.cg.shared.global [%0], [%1], 16;" :: "r"(dst), "l"(src));
}
__device__ __forceinline__ void cp_commit() {
    asm volatile("cp.async.commit_group;" ::: "memory");
}
__device__ __forceinline__ void ldmatrix_x4(uint32_t* d, uint32_t addr) {
    asm volatile("ldmatrix.sync.aligned.m8n8.x4.shared.b16 {%0,%1,%2,%3}, [%4];"
                 : "=r"(d[0]), "=r"(d[1]), "=r"(d[2]), "=r"(d[3]) : "r"(addr));
}
__device__ __forceinline__ void mma16816(float* c, const uint32_t* a,
                                         uint32_t b0, uint32_t b1) {
    asm volatile(
        "mma.sync.aligned.m16n8k16.row.col.f32.f16.f16.f32 "
        "{%0,%1,%2,%3}, {%4,%5,%6,%7}, {%8,%9}, {%0,%1,%2,%3};"
        : "+f"(c[0]), "+f"(c[1]), "+f"(c[2]), "+f"(c[3])
        : "r"(a[0]), "r"(a[1]), "r"(a[2]), "r"(a[3]), "r"(b0), "r"(b1));
}
__device__ __forceinline__ uint32_t packh2(float x, float y) {
    __half2 h = __floats2half2_rn(x, y);
    return *reinterpret_cast<uint32_t*>(&h);
}

// ---------------------------------------------------------------------------
// conv_a: fp32 [M,1024] -> fp16 row-major g_a16 (coalesced both sides)
// ---------------------------------------------------------------------------
__global__ __launch_bounds__(256) void conv_a_kernel(const float* __restrict__ src)
{
    const int m  = blockIdx.x;
    const int k4 = threadIdx.x << 2;
    float4 v = *(const float4*)(src + (size_t)m * E_ + k4);
    uint2 o;
    o.x = packh2(v.x, v.y);
    o.y = packh2(v.z, v.w);
    *(uint2*)&g_a16[(size_t)m * E_ + k4] = o;
}

// ---------------------------------------------------------------------------
// conv_w: W [1024][Ncols] fp32 -> W^T fp16 via 64x64 smem transpose tile.
// Coalesced 256B row reads, coalesced uint2 writes.
// ---------------------------------------------------------------------------
__global__ __launch_bounds__(256) void conv_w_kernel(
    const float* __restrict__ W, int Ncols, int which)
{
    __shared__ float tile[64][65];
    __half* dst = which ? g_wp16 : g_wq16;
    const int k0 = blockIdx.x * 64;
    const int n0 = blockIdx.y * 64;
    const int tid = threadIdx.x;

    const int lr = tid >> 6;        // 0..3
    const int lc = tid & 63;        // 0..63
#pragma unroll
    for (int i = 0; i < 16; i++) {
        const int r = lr + i * 4;
        tile[r][lc] = W[(size_t)(k0 + r) * Ncols + n0 + lc];
    }
    __syncthreads();

    const int nl = tid >> 2;        // 0..63
    const int kc = (tid & 3) << 4;  // 0,16,32,48
#pragma unroll
    for (int j = 0; j < 16; j += 4) {
        uint2 o;
        o.x = packh2(tile[kc + j][nl],     tile[kc + j + 1][nl]);
        o.y = packh2(tile[kc + j + 2][nl], tile[kc + j + 3][nl]);
        *(uint2*)&dst[(size_t)(n0 + nl) * E_ + k0 + kc + j] = o;
    }
}

// ---------------------------------------------------------------------------
// fp16 HMMA GEMM (unchanged from round 8 — at the legacy-MMA ceiling).
// CTA 128x128, 4 warps (64x64), 3-stage cp.async, 1 barrier/k-iter, reg-dbuf.
// mode 0: write Q/K fp16 [B,H,N,D] + V^T fp16 [B,H,D,N]; mode 1: fp32 out.
// ---------------------------------------------------------------------------
#define GEMM_SMEM (3 * 32768)

__device__ __forceinline__ void load_tile(
    uint32_t sbase, int stage, int ktile,
    const __half* A, const __half* Bt, int m0, int n0, int tid)
{
    const char* aSrc = (const char*)(A  + (size_t)m0 * E_ + ktile * 64);
    const char* bSrc = (const char*)(Bt + (size_t)n0 * E_ + ktile * 64);
    const uint32_t sa  = sbase + stage * 32768;
    const uint32_t sbB = sa + 16384;
#pragma unroll
    for (int i = 0; i < 8; i++) {
        const int u = i * 128 + tid;
        const int r = u >> 3, c = u & 7;
        cp_async16(sa + r * 128 + ((c ^ (r & 7)) << 4),
                   aSrc + (size_t)r * (E_ * 2) + c * 16);
    }
#pragma unroll
    for (int i = 0; i < 8; i++) {
        const int u = i * 128 + tid;
        const int r = u >> 3, c = u & 7;
        cp_async16(sbB + r * 128 + ((c ^ (r & 7)) << 4),
                   bSrc + (size_t)r * (E_ * 2) + c * 16);
    }
    cp_commit();
}

__global__ __launch_bounds__(128) void hgemm_kernel(
    const float* __restrict__ bias, float* __restrict__ out, int mode)
{
    extern __shared__ char smem[];
    const uint32_t sb = smem_u32(smem);
    const __half* A  = g_a16;
    const __half* Bt = (mode == 0) ? g_wq16 : g_wp16;

    const int tid  = threadIdx.x;
    const int lane = tid & 31, wid = tid >> 5;
    const int warp_m = wid & 1, warp_n = wid >> 1;
    const int m0 = blockIdx.y * 128, n0 = blockIdx.x * 128;

    float acc[4][8][4];
#pragma unroll
    for (int i = 0; i < 4; i++)
#pragma unroll
        for (int j = 0; j < 8; j++)
#pragma unroll
            for (int r = 0; r < 4; r++) acc[i][j][r] = 0.f;

    load_tile(sb, 0, 0, A, Bt, m0, n0, tid);
    load_tile(sb, 1, 1, A, Bt, m0, n0, tid);

    const int lane15 = lane & 15, lhalf = lane >> 4;
    const int ra  = warp_m * 64 + lane15;
    const int rbw = warp_n * 64 + lane15;

    for (int kt = 0; kt < KT_; kt++) {
        asm volatile("cp.async.wait_group 1;" ::: "memory");
        __syncthreads();
        if (kt + 2 < KT_)
            load_tile(sb, (kt + 2) % 3, kt + 2, A, Bt, m0, n0, tid);
        else
            cp_commit();

        const uint32_t sa  = sb + (kt % 3) * 32768;
        const uint32_t sbB = sa + 16384;

        uint32_t afr[2][4][4], bfr[2][4][4];
        {
            const int kc = lhalf;
#pragma unroll
            for (int mi = 0; mi < 4; mi++) {
                const int r = ra + mi * 16;
                ldmatrix_x4(afr[0][mi], sa + r * 128 + ((kc ^ (r & 7)) << 4));
            }
#pragma unroll
            for (int ng = 0; ng < 4; ng++) {
                const int r = rbw + ng * 16;
                ldmatrix_x4(bfr[0][ng], sbB + r * 128 + ((kc ^ (r & 7)) << 4));
            }
        }
#pragma unroll
        for (int kk = 0; kk < 4; kk++) {
            const int cur = kk & 1, nxt = cur ^ 1;
            if (kk < 3) {
                const int kc = (kk + 1) * 2 + lhalf;
#pragma unroll
                for (int mi = 0; mi < 4; mi++) {
                    const int r = ra + mi * 16;
                    ldmatrix_x4(afr[nxt][mi], sa + r * 128 + ((kc ^ (r & 7)) << 4));
                }
#pragma unroll
                for (int ng = 0; ng < 4; ng++) {
                    const int r = rbw + ng * 16;
                    ldmatrix_x4(bfr[nxt][ng], sbB + r * 128 + ((kc ^ (r & 7)) << 4));
                }
            }
#pragma unroll
            for (int mi = 0; mi < 4; mi++)
#pragma unroll
                for (int nj = 0; nj < 8; nj++)
                    mma16816(acc[mi][nj], afr[cur][mi],
                             bfr[cur][nj >> 1][nj & 1],
                             bfr[cur][nj >> 1][(nj & 1) + 2]);
        }
    }

    const int mrow = m0 + warp_m * 64 + (lane >> 2);
    const int ncb  = n0 + warp_n * 64 + (lane & 3) * 2;
#pragma unroll
    for (int mi = 0; mi < 4; mi++) {
#pragma unroll
        for (int nj = 0; nj < 8; nj++) {
            const int c  = ncb + nj * 8;
            const float b0 = bias[c], b1 = bias[c + 1];
            const int r0 = mrow + mi * 16;
            const float v00 = acc[mi][nj][0] + b0, v01 = acc[mi][nj][1] + b1;
            const float v10 = acc[mi][nj][2] + b0, v11 = acc[mi][nj][3] + b1;
            if (mode == 1) {
                float2 p0; p0.x = v00; p0.y = v01;
                float2 p1; p1.x = v10; p1.y = v11;
                *(float2*)&out[(size_t)r0 * E_ + c] = p0;
                *(float2*)&out[(size_t)(r0 + 8) * E_ + c] = p1;
                continue;
            }
            const int sec = c >> 10, e = c & 1023;
            const int hh = e >> 6, dd = e & 63;
            const int bb = r0 >> 10, nn = r0 & 1023;
            if (sec <= 1) {
                __half* dq = sec == 0 ? g_q16 : g_k16;
                const size_t i0 = (((size_t)bb * H_ + hh) * N_ + nn) * D_ + dd;
                *(uint32_t*)&dq[i0]          = packh2(v00, v01);
                *(uint32_t*)&dq[i0 + 8 * D_] = packh2(v10, v11);
            } else {
                const size_t i00 = (((size_t)bb * H_ + hh) * D_ + dd) * N_ + nn;
                g_vt16[i00]          = __float2half_rn(v00);
                g_vt16[i00 + N_]     = __float2half_rn(v01);
                g_vt16[i00 + 8]      = __float2half_rn(v10);
                g_vt16[i00 + N_ + 8] = __float2half_rn(v11);
            }
        }
    }
}

// ---------------------------------------------------------------------------
// Flash attention, fp16 HMMA. 128 q-rows per CTA (8 warps x 16 rows),
// 2-stage pipeline. stage: K @0 (8KB), V^T @8192 (8KB); stride 16384.
// ---------------------------------------------------------------------------
#define ATT_SMEM (2 * 16384)

__device__ __forceinline__ void att_load_tile(
    uint32_t st, int kv0, const __half* k16, const __half* vt16, int tid)
{
#pragma unroll
    for (int i = 0; i < 2; i++) {
        const int u = i * 256 + tid;
        const int r = u >> 3, c = u & 7;
        const uint32_t soff = r * 128 + ((c ^ (r & 7)) << 4);
        cp_async16(st + soff,        (const char*)k16  + (size_t)(kv0 + r) * 128 + c * 16);
        cp_async16(st + 8192 + soff, (const char*)vt16 + (size_t)r * 2048 + kv0 * 2 + c * 16);
    }
    cp_commit();
}

__global__ __launch_bounds__(256) void attn_kernel()
{
    extern __shared__ char smem[];
    const uint32_t sb = smem_u32(smem);

    const int tid = threadIdx.x;
    const int lane = tid & 31, w = tid >> 5;           // 8 warps
    const int lane15 = lane & 15, lhalf = lane >> 4;
    const int q0 = blockIdx.x * 128;
    const int h  = blockIdx.y;
    const int b  = blockIdx.z;

    const size_t hb = (size_t)(b * H_ + h) * (N_ * D_);
    const __half* q16  = g_q16  + hb;
    const __half* k16  = g_k16  + hb;
    const __half* vt16 = g_vt16 + hb;

    // stage 128 Q rows (16KB, spans stage-0 region), extract fragments
#pragma unroll
    for (int i = 0; i < 4; i++) {
        const int u = i * 256 + tid;
        const int r = u >> 3, c = u & 7;
        cp_async16(sb + r * 128 + ((c ^ (r & 7)) << 4),
                   (const char*)q16 + (size_t)(q0 + r) * 128 + c * 16);
    }
    cp_commit();
    asm volatile("cp.async.wait_group 0;" ::: "memory");
    __syncthreads();

    uint32_t qf[4][4];
    {
        const int r = w * 16 + lane15;
#pragma unroll
        for (int t = 0; t < 4; t++)
            ldmatrix_x4(qf[t], sb + r * 128 + (((t * 2 + lhalf) ^ (r & 7)) << 4));
    }
    __syncthreads();

    float mstate[2] = {-1e30f, -1e30f};
    float lstate[2] = {0.f, 0.f};
    float oacc[8][4];
#pragma unroll
    for (int j = 0; j < 8; j++)
#pragma unroll
        for (int r = 0; r < 4; r++) oacc[j][r] = 0.f;

    const float cexp = 0.18033688f;   // D^-0.5 * log2(e)

    att_load_tile(sb, 0, k16, vt16, tid);
    att_load_tile(sb + 16384, 64, k16, vt16, tid);

    for (int t = 0; t < 16; t++) {
        asm volatile("cp.async.wait_group 1;" ::: "memory");
        __syncthreads();
        const uint32_t stK = sb + (t & 1) * 16384;
        const uint32_t stV = stK + 8192;

        float sacc[8][4];
#pragma unroll
        for (int j = 0; j < 8; j++)
#pragma unroll
            for (int r = 0; r < 4; r++) sacc[j][r] = 0.f;

#pragma unroll
        for (int kvg = 0; kvg < 4; kvg++) {
            const int rb = kvg * 16 + lane15;
#pragma unroll
            for (int kk = 0; kk < 4; kk++) {
                uint32_t bf[4];
                ldmatrix_x4(bf, stK + rb * 128 + (((kk * 2 + lhalf) ^ (rb & 7)) << 4));
                mma16816(sacc[2 * kvg],     qf[kk], bf[0], bf[2]);
                mma16816(sacc[2 * kvg + 1], qf[kk], bf[1], bf[3]);
            }
        }

#pragma unroll
        for (int rr = 0; rr < 2; rr++) {
            float mx = -1e30f;
#pragma unroll
            for (int j = 0; j < 8; j++)
                mx = fmaxf(mx, fmaxf(sacc[j][rr * 2], sacc[j][rr * 2 + 1]));
            mx = fmaxf(mx, __shfl_xor_sync(0xffffffffu, mx, 1));
            mx = fmaxf(mx, __shfl_xor_sync(0xffffffffu, mx, 2));
            const float mnew  = fmaxf(mstate[rr], mx);
            const float alpha = exp2f((mstate[rr] - mnew) * cexp);
            mstate[rr] = mnew;
            float rs = 0.f;
#pragma unroll
            for (int j = 0; j < 8; j++) {
                const float p0 = exp2f((sacc[j][rr * 2]     - mnew) * cexp);
                const float p1 = exp2f((sacc[j][rr * 2 + 1] - mnew) * cexp);
                sacc[j][rr * 2] = p0; sacc[j][rr * 2 + 1] = p1;
                rs += p0 + p1;
            }
            rs += __shfl_xor_sync(0xffffffffu, rs, 1);
            rs += __shfl_xor_sync(0xffffffffu, rs, 2);
            lstate[rr] = lstate[rr] * alpha + rs;
#pragma unroll
            for (int j = 0; j < 8; j++) {
                oacc[j][rr * 2]     *= alpha;
                oacc[j][rr * 2 + 1] *= alpha;
            }
        }

        // P fragments in registers (C-frag layout == A-frag layout)
        uint32_t pf[4][4];
#pragma unroll
        for (int kk = 0; kk < 4; kk++) {
#pragma unroll
            for (int q = 0; q < 4; q++) {
                const int tile = 2 * kk + (q >> 1);
                const int ri   = (q & 1) * 2;
                pf[kk][q] = packh2(sacc[tile][ri], sacc[tile][ri + 1]);
            }
        }

#pragma unroll
        for (int dg = 0; dg < 4; dg++) {
            const int rb = dg * 16 + lane15;
#pragma unroll
            for (int kk = 0; kk < 4; kk++) {
                uint32_t bf[4];
                ldmatrix_x4(bf, stV + rb * 128 + (((kk * 2 + lhalf) ^ (rb & 7)) << 4));
                mma16816(oacc[2 * dg],     pf[kk], bf[0], bf[2]);
                mma16816(oacc[2 * dg + 1], pf[kk], bf[1], bf[3]);
            }
        }

        __syncthreads();
        if (t + 2 < 16)
            att_load_tile(sb + (t & 1) * 16384, (t + 2) * 64, k16, vt16, tid);
        else
            cp_commit();
    }

    // epilogue: normalize, write fp16 O rows into g_a16 [M, E]
    const float inv0 = 1.f / lstate[0];
    const float inv1 = 1.f / lstate[1];
    const int qrow = q0 + w * 16 + (lane >> 2);
    const size_t m0r = (size_t)(b * N_ + qrow) * E_;
    const size_t m1r = m0r + (size_t)8 * E_;
    const int colb = h * 64 + 2 * (lane & 3);
#pragma unroll
    for (int j = 0; j < 8; j++) {
        const int col = colb + 8 * j;
        *(uint32_t*)&g_a16[m0r + col] = packh2(oacc[j][0] * inv0, oacc[j][1] * inv0);
        *(uint32_t*)&g_a16[m1r + col] = packh2(oacc[j][2] * inv1, oacc[j][3] * inv1);
    }
}

// ---------------------------------------------------------------------------
extern "C" void kernel_launch(void* const* d_in, const int* in_sizes, int n_in,
                              void* d_out, int out_size)
{
    const float* x  = (const float*)d_in[0];
    const float* Wq = (const float*)d_in[1];
    const float* bq = (const float*)d_in[2];
    const float* Wp = (const float*)d_in[3];
    const float* bp = (const float*)d_in[4];
    float* out = (float*)d_out;

    cudaFuncSetAttribute(hgemm_kernel,
                         cudaFuncAttributeMaxDynamicSharedMemorySize, GEMM_SMEM);
    cudaFuncSetAttribute(attn_kernel,
                         cudaFuncAttributeMaxDynamicSharedMemorySize, ATT_SMEM);

    conv_a_kernel<<<M_, 256>>>(x);
    conv_w_kernel<<<dim3(E_ / 64, QKV_N / 64), 256>>>(Wq, QKV_N, 0);
    conv_w_kernel<<<dim3(E_ / 64, E_ / 64), 256>>>(Wp, E_, 1);

    hgemm_kernel<<<dim3(QKV_N / 128, M_ / 128), 128, GEMM_SMEM>>>(bq, out, 0);

    attn_kernel<<<dim3(N_ / 128, H_, B_), 256, ATT_SMEM>>>();

    hgemm_kernel<<<dim3(E_ / 128, M_ / 128), 128, GEMM_SMEM>>>(bp, out, 1);
}

// round 10
// speedup vs baseline: 2.8030x; 1.0324x over previous
#include <cuda_runtime.h>
#include <cuda_fp16.h>
#include <cstdint>

#define B_   16
#define N_   1024
#define E_   1024
#define H_   16
#define D_   64
#define M_   (B_ * N_)        // 16384
#define QKV_N (3 * E_)        // 3072
#define KT_   (E_ / 64)       // 16 k-iters of 64

// ---------------------------------------------------------------------------
// Scratch (__device__ globals; no allocations)
// ---------------------------------------------------------------------------
static __device__ __align__(1024) __half g_q16 [(size_t)B_ * H_ * N_ * D_];
static __device__ __align__(1024) __half g_k16 [(size_t)B_ * H_ * N_ * D_];
static __device__ __align__(1024) __half g_vt16[(size_t)B_ * H_ * D_ * N_];  // V^T [B,H,D,N]
static __device__ __align__(1024) __half g_a16 [(size_t)M_ * E_];    // x, then attn out
static __device__ __align__(1024) __half g_wq16[(size_t)QKV_N * E_]; // Wqkv^T (n-major)
static __device__ __align__(1024) __half g_wp16[(size_t)E_ * E_];    // Wproj^T (n-major)

// ---------------------------------------------------------------------------
// helpers
// ---------------------------------------------------------------------------
__device__ __forceinline__ uint32_t smem_u32(const void* p) {
    uint32_t a;
    asm("{ .reg .u64 t; cvta.to.shared.u64 t, %1; cvt.u32.u64 %0, t; }"
        : "=r"(a) : "l"(p));
    return a;
}
__device__ __forceinline__ void cp_async16(uint32_t dst, const void* src) {
    asm volatile("cp.async.cg.shared.global [%0], [%1], 16;" :: "r"(dst), "l"(src));
}
__device__ __forceinline__ void cp_commit() {
    asm volatile("cp.async.commit_group;" ::: "memory");
}
__device__ __forceinline__ void ldmatrix_x4(uint32_t* d, uint32_t addr) {
    asm volatile("ldmatrix.sync.aligned.m8n8.x4.shared.b16 {%0,%1,%2,%3}, [%4];"
                 : "=r"(d[0]), "=r"(d[1]), "=r"(d[2]), "=r"(d[3]) : "r"(addr));
}
__device__ __forceinline__ void mma16816(float* c, const uint32_t* a,
                                         uint32_t b0, uint32_t b1) {
    asm volatile(
        "mma.sync.aligned.m16n8k16.row.col.f32.f16.f16.f32 "
        "{%0,%1,%2,%3}, {%4,%5,%6,%7}, {%8,%9}, {%0,%1,%2,%3};"
        : "+f"(c[0]), "+f"(c[1]), "+f"(c[2]), "+f"(c[3])
        : "r"(a[0]), "r"(a[1]), "r"(a[2]), "r"(a[3]), "r"(b0), "r"(b1));
}
__device__ __forceinline__ uint32_t packh2(float x, float y) {
    __half2 h = __floats2half2_rn(x, y);
    return *reinterpret_cast<uint32_t*>(&h);
}
#define MBAR_INIT(addr, cnt) \
    asm volatile("mbarrier.init.shared.b64 [%0], %1;" :: "r"(addr), "r"(cnt) : "memory")
#define MBAR_ARRIVE(addr) \
    asm volatile("mbarrier.arrive.shared.b64 _, [%0];" :: "r"(addr) : "memory")
#define MBAR_ARRIVE_CPASYNC(addr) \
    asm volatile("cp.async.mbarrier.arrive.noinc.shared.b64 [%0];" :: "r"(addr) : "memory")
#define MBAR_WAIT(addr, parity) do {                                          \
    asm volatile(                                                             \
        "{\n\t.reg .pred P1;\n\t"                                             \
        "WAIT_%=:\n\t"                                                        \
        "mbarrier.try_wait.parity.acquire.cta.shared::cta.b64 P1, [%0], %1, 0x989680;\n\t" \
        "@P1 bra.uni DONE_%=;\n\t"                                            \
        "bra.uni WAIT_%=;\n\t"                                                \
        "DONE_%=:\n\t}"                                                       \
        :: "r"(addr), "r"(parity) : "memory");                                \
} while (0)

// ---------------------------------------------------------------------------
// conv_a: fp32 [M,1024] -> fp16 row-major g_a16
// ---------------------------------------------------------------------------
__global__ __launch_bounds__(256) void conv_a_kernel(const float* __restrict__ src)
{
    const int m  = blockIdx.x;
    const int k4 = threadIdx.x << 2;
    float4 v = *(const float4*)(src + (size_t)m * E_ + k4);
    uint2 o;
    o.x = packh2(v.x, v.y);
    o.y = packh2(v.z, v.w);
    *(uint2*)&g_a16[(size_t)m * E_ + k4] = o;
}

// ---------------------------------------------------------------------------
// conv_w: W [1024][Ncols] fp32 -> W^T fp16 via 64x64 smem transpose tile.
// ---------------------------------------------------------------------------
__global__ __launch_bounds__(256) void conv_w_kernel(
    const float* __restrict__ W, int Ncols, int which)
{
    __shared__ float tile[64][65];
    __half* dst = which ? g_wp16 : g_wq16;
    const int k0 = blockIdx.x * 64;
    const int n0 = blockIdx.y * 64;
    const int tid = threadIdx.x;

    const int lr = tid >> 6;
    const int lc = tid & 63;
#pragma unroll
    for (int i = 0; i < 16; i++) {
        const int r = lr + i * 4;
        tile[r][lc] = W[(size_t)(k0 + r) * Ncols + n0 + lc];
    }
    __syncthreads();

    const int nl = tid >> 2;
    const int kc = (tid & 3) << 4;
#pragma unroll
    for (int j = 0; j < 16; j += 4) {
        uint2 o;
        o.x = packh2(tile[kc + j][nl],     tile[kc + j + 1][nl]);
        o.y = packh2(tile[kc + j + 2][nl], tile[kc + j + 3][nl]);
        *(uint2*)&dst[(size_t)(n0 + nl) * E_ + k0 + kc + j] = o;
    }
}

// ---------------------------------------------------------------------------
// fp16 HMMA GEMM, producer/consumer mbarrier pipeline (NO __syncthreads in
// the mainloop — consumer warps run desynchronized).
// CTA 128x128. Warps 0-3: consumers (64x64 tiles, reg-dbuf fragments).
// Warp 4: producer (issues all cp.async; arms full[s] via
// cp.async.mbarrier.arrive.noinc).
// 3-stage ring, stage = 32KB (A 16KB @0, B 16KB @16384).
// smem: [0,48) barriers (full[s]@s*16, empty[s]@s*16+8), stages @1024.
// mode 0: write Q/K fp16 [B,H,N,D] + V^T fp16 [B,H,D,N]; mode 1: fp32 out.
// ---------------------------------------------------------------------------
#define GEMM_SMEM (1024 + 3 * 32768)

__global__ __launch_bounds__(160) void hgemm_kernel(
    const float* __restrict__ bias, float* __restrict__ out, int mode)
{
    extern __shared__ char smem[];
    const uint32_t sb = smem_u32(smem);
    const __half* A  = g_a16;
    const __half* Bt = (mode == 0) ? g_wq16 : g_wp16;

    const int tid  = threadIdx.x;
    const int lane = tid & 31, wid = tid >> 5;
    const int m0 = blockIdx.y * 128, n0 = blockIdx.x * 128;

    if (tid == 0) {
#pragma unroll
        for (int s = 0; s < 3; s++) {
            MBAR_INIT(sb + s * 16, 32);       // full: 32 producer threads
            MBAR_INIT(sb + s * 16 + 8, 128);  // empty: 128 consumer threads
        }
    }
    __syncthreads();   // the ONLY block-wide barrier

    if (wid == 4) {
        // ------------------------- producer warp -------------------------
        const char* aBase = (const char*)(A  + (size_t)m0 * E_);
        const char* bBase = (const char*)(Bt + (size_t)n0 * E_);
        for (int t = 0; t < KT_; t++) {
            const int s = t % 3;
            if (t >= 3) MBAR_WAIT(sb + s * 16 + 8, ((t - 3) / 3) & 1);
            const uint32_t sa  = sb + 1024 + s * 32768;
            const char* aSrc = aBase + t * 128;
            const char* bSrc = bBase + t * 128;
#pragma unroll
            for (int i = 0; i < 32; i++) {
                const int u = i * 32 + lane;
                const int r = u >> 3, c = u & 7;
                cp_async16(sa + r * 128 + ((c ^ (r & 7)) << 4),
                           aSrc + (size_t)r * (E_ * 2) + c * 16);
            }
#pragma unroll
            for (int i = 0; i < 32; i++) {
                const int u = i * 32 + lane;
                const int r = u >> 3, c = u & 7;
                cp_async16(sa + 16384 + r * 128 + ((c ^ (r & 7)) << 4),
                           bSrc + (size_t)r * (E_ * 2) + c * 16);
            }
            MBAR_ARRIVE_CPASYNC(sb + s * 16);
        }
        return;
    }

    // --------------------------- consumer warps ---------------------------
    const int warp_m = wid & 1, warp_n = wid >> 1;

    float acc[4][8][4];
#pragma unroll
    for (int i = 0; i < 4; i++)
#pragma unroll
        for (int j = 0; j < 8; j++)
#pragma unroll
            for (int r = 0; r < 4; r++) acc[i][j][r] = 0.f;

    const int lane15 = lane & 15, lhalf = lane >> 4;
    const int ra  = warp_m * 64 + lane15;
    const int rbw = warp_n * 64 + lane15;

    for (int kt = 0; kt < KT_; kt++) {
        const int s = kt % 3;
        MBAR_WAIT(sb + s * 16, (kt / 3) & 1);   // full[s]

        const uint32_t sa  = sb + 1024 + s * 32768;
        const uint32_t sbB = sa + 16384;

        uint32_t afr[2][4][4], bfr[2][4][4];
        {
            const int kc = lhalf;
#pragma unroll
            for (int mi = 0; mi < 4; mi++) {
                const int r = ra + mi * 16;
                ldmatrix_x4(afr[0][mi], sa + r * 128 + ((kc ^ (r & 7)) << 4));
            }
#pragma unroll
            for (int ng = 0; ng < 4; ng++) {
                const int r = rbw + ng * 16;
                ldmatrix_x4(bfr[0][ng], sbB + r * 128 + ((kc ^ (r & 7)) << 4));
            }
        }
#pragma unroll
        for (int kk = 0; kk < 4; kk++) {
            const int cur = kk & 1, nxt = cur ^ 1;
            if (kk < 3) {
                const int kc = (kk + 1) * 2 + lhalf;
#pragma unroll
                for (int mi = 0; mi < 4; mi++) {
                    const int r = ra + mi * 16;
                    ldmatrix_x4(afr[nxt][mi], sa + r * 128 + ((kc ^ (r & 7)) << 4));
                }
#pragma unroll
                for (int ng = 0; ng < 4; ng++) {
                    const int r = rbw + ng * 16;
                    ldmatrix_x4(bfr[nxt][ng], sbB + r * 128 + ((kc ^ (r & 7)) << 4));
                }
            }
#pragma unroll
            for (int mi = 0; mi < 4; mi++)
#pragma unroll
                for (int nj = 0; nj < 8; nj++)
                    mma16816(acc[mi][nj], afr[cur][mi],
                             bfr[cur][nj >> 1][nj & 1],
                             bfr[cur][nj >> 1][(nj & 1) + 2]);
        }
        MBAR_ARRIVE(sb + s * 16 + 8);           // empty[s]
    }

    // Epilogue (consumers only)
    const int mrow = m0 + warp_m * 64 + (lane >> 2);
    const int ncb  = n0 + warp_n * 64 + (lane & 3) * 2;
#pragma unroll
    for (int mi = 0; mi < 4; mi++) {
#pragma unroll
        for (int nj = 0; nj < 8; nj++) {
            const int c  = ncb + nj * 8;
            const float b0 = bias[c], b1 = bias[c + 1];
            const int r0 = mrow + mi * 16;
            const float v00 = acc[mi][nj][0] + b0, v01 = acc[mi][nj][1] + b1;
            const float v10 = acc[mi][nj][2] + b0, v11 = acc[mi][nj][3] + b1;
            if (mode == 1) {
                float2 p0; p0.x = v00; p0.y = v01;
                float2 p1; p1.x = v10; p1.y = v11;
                *(float2*)&out[(size_t)r0 * E_ + c] = p0;
                *(float2*)&out[(size_t)(r0 + 8) * E_ + c] = p1;
                continue;
            }
            const int sec = c >> 10, e = c & 1023;
            const int hh = e >> 6, dd = e & 63;
            const int bb = r0 >> 10, nn = r0 & 1023;
            if (sec <= 1) {
                __half* dq = sec == 0 ? g_q16 : g_k16;
                const size_t i0 = (((size_t)bb * H_ + hh) * N_ + nn) * D_ + dd;
                *(uint32_t*)&dq[i0]          = packh2(v00, v01);
                *(uint32_t*)&dq[i0 + 8 * D_] = packh2(v10, v11);
            } else {
                const size_t i00 = (((size_t)bb * H_ + hh) * D_ + dd) * N_ + nn;
                g_vt16[i00]          = __float2half_rn(v00);
                g_vt16[i00 + N_]     = __float2half_rn(v01);
                g_vt16[i00 + 8]      = __float2half_rn(v10);
                g_vt16[i00 + N_ + 8] = __float2half_rn(v11);
            }
        }
    }
}

// ---------------------------------------------------------------------------
// Flash attention, fp16 HMMA (unchanged from round 9).
// 128 q-rows per CTA (8 warps), 2-stage cp.async pipeline.
// ---------------------------------------------------------------------------
#define ATT_SMEM (2 * 16384)

__device__ __forceinline__ void att_load_tile(
    uint32_t st, int kv0, const __half* k16, const __half* vt16, int tid)
{
#pragma unroll
    for (int i = 0; i < 2; i++) {
        const int u = i * 256 + tid;
        const int r = u >> 3, c = u & 7;
        const uint32_t soff = r * 128 + ((c ^ (r & 7)) << 4);
        cp_async16(st + soff,        (const char*)k16  + (size_t)(kv0 + r) * 128 + c * 16);
        cp_async16(st + 8192 + soff, (const char*)vt16 + (size_t)r * 2048 + kv0 * 2 + c * 16);
    }
    cp_commit();
}

__global__ __launch_bounds__(256) void attn_kernel()
{
    extern __shared__ char smem[];
    const uint32_t sb = smem_u32(smem);

    const int tid = threadIdx.x;
    const int lane = tid & 31, w = tid >> 5;
    const int lane15 = lane & 15, lhalf = lane >> 4;
    const int q0 = blockIdx.x * 128;
    const int h  = blockIdx.y;
    const int b  = blockIdx.z;

    const size_t hb = (size_t)(b * H_ + h) * (N_ * D_);
    const __half* q16  = g_q16  + hb;
    const __half* k16  = g_k16  + hb;
    const __half* vt16 = g_vt16 + hb;

#pragma unroll
    for (int i = 0; i < 4; i++) {
        const int u = i * 256 + tid;
        const int r = u >> 3, c = u & 7;
        cp_async16(sb + r * 128 + ((c ^ (r & 7)) << 4),
                   (const char*)q16 + (size_t)(q0 + r) * 128 + c * 16);
    }
    cp_commit();
    asm volatile("cp.async.wait_group 0;" ::: "memory");
    __syncthreads();

    uint32_t qf[4][4];
    {
        const int r = w * 16 + lane15;
#pragma unroll
        for (int t = 0; t < 4; t++)
            ldmatrix_x4(qf[t], sb + r * 128 + (((t * 2 + lhalf) ^ (r & 7)) << 4));
    }
    __syncthreads();

    float mstate[2] = {-1e30f, -1e30f};
    float lstate[2] = {0.f, 0.f};
    float oacc[8][4];
#pragma unroll
    for (int j = 0; j < 8; j++)
#pragma unroll
        for (int r = 0; r < 4; r++) oacc[j][r] = 0.f;

    const float cexp = 0.18033688f;   // D^-0.5 * log2(e)

    att_load_tile(sb, 0, k16, vt16, tid);
    att_load_tile(sb + 16384, 64, k16, vt16, tid);

    for (int t = 0; t < 16; t++) {
        asm volatile("cp.async.wait_group 1;" ::: "memory");
        __syncthreads();
        const uint32_t stK = sb + (t & 1) * 16384;
        const uint32_t stV = stK + 8192;

        float sacc[8][4];
#pragma unroll
        for (int j = 0; j < 8; j++)
#pragma unroll
            for (int r = 0; r < 4; r++) sacc[j][r] = 0.f;

#pragma unroll
        for (int kvg = 0; kvg < 4; kvg++) {
            const int rb = kvg * 16 + lane15;
#pragma unroll
            for (int kk = 0; kk < 4; kk++) {
                uint32_t bf[4];
                ldmatrix_x4(bf, stK + rb * 128 + (((kk * 2 + lhalf) ^ (rb & 7)) << 4));
                mma16816(sacc[2 * kvg],     qf[kk], bf[0], bf[2]);
                mma16816(sacc[2 * kvg + 1], qf[kk], bf[1], bf[3]);
            }
        }

#pragma unroll
        for (int rr = 0; rr < 2; rr++) {
            float mx = -1e30f;
#pragma unroll
            for (int j = 0; j < 8; j++)
                mx = fmaxf(mx, fmaxf(sacc[j][rr * 2], sacc[j][rr * 2 + 1]));
            mx = fmaxf(mx, __shfl_xor_sync(0xffffffffu, mx, 1));
            mx = fmaxf(mx, __shfl_xor_sync(0xffffffffu, mx, 2));
            const float mnew  = fmaxf(mstate[rr], mx);
            const float alpha = exp2f((mstate[rr] - mnew) * cexp);
            mstate[rr] = mnew;
            float rs = 0.f;
#pragma unroll
            for (int j = 0; j < 8; j++) {
                const float p0 = exp2f((sacc[j][rr * 2]     - mnew) * cexp);
                const float p1 = exp2f((sacc[j][rr * 2 + 1] - mnew) * cexp);
                sacc[j][rr * 2] = p0; sacc[j][rr * 2 + 1] = p1;
                rs += p0 + p1;
            }
            rs += __shfl_xor_sync(0xffffffffu, rs, 1);
            rs += __shfl_xor_sync(0xffffffffu, rs, 2);
            lstate[rr] = lstate[rr] * alpha + rs;
#pragma unroll
            for (int j = 0; j < 8; j++) {
                oacc[j][rr * 2]     *= alpha;
                oacc[j][rr * 2 + 1] *= alpha;
            }
        }

        uint32_t pf[4][4];
#pragma unroll
        for (int kk = 0; kk < 4; kk++) {
#pragma unroll
            for (int q = 0; q < 4; q++) {
                const int tile = 2 * kk + (q >> 1);
                const int ri   = (q & 1) * 2;
                pf[kk][q] = packh2(sacc[tile][ri], sacc[tile][ri + 1]);
            }
        }

#pragma unroll
        for (int dg = 0; dg < 4; dg++) {
            const int rb = dg * 16 + lane15;
#pragma unroll
            for (int kk = 0; kk < 4; kk++) {
                uint32_t bf[4];
                ldmatrix_x4(bf, stV + rb * 128 + (((kk * 2 + lhalf) ^ (rb & 7)) << 4));
                mma16816(oacc[2 * dg],     pf[kk], bf[0], bf[2]);
                mma16816(oacc[2 * dg + 1], pf[kk], bf[1], bf[3]);
            }
        }

        __syncthreads();
        if (t + 2 < 16)
            att_load_tile(sb + (t & 1) * 16384, (t + 2) * 64, k16, vt16, tid);
        else
            cp_commit();
    }

    const float inv0 = 1.f / lstate[0];
    const float inv1 = 1.f / lstate[1];
    const int qrow = q0 + w * 16 + (lane >> 2);
    const size_t m0r = (size_t)(b * N_ + qrow) * E_;
    const size_t m1r = m0r + (size_t)8 * E_;
    const int colb = h * 64 + 2 * (lane & 3);
#pragma unroll
    for (int j = 0; j < 8; j++) {
        const int col = colb + 8 * j;
        *(uint32_t*)&g_a16[m0r + col] = packh2(oacc[j][0] * inv0, oacc[j][1] * inv0);
        *(uint32_t*)&g_a16[m1r + col] = packh2(oacc[j][2] * inv1, oacc[j][3] * inv1);
    }
}

// ---------------------------------------------------------------------------
extern "C" void kernel_launch(void* const* d_in, const int* in_sizes, int n_in,
                              void* d_out, int out_size)
{
    const float* x  = (const float*)d_in[0];
    const float* Wq = (const float*)d_in[1];
    const float* bq = (const float*)d_in[2];
    const float* Wp = (const float*)d_in[3];
    const float* bp = (const float*)d_in[4];
    float* out = (float*)d_out;

    cudaFuncSetAttribute(hgemm_kernel,
                         cudaFuncAttributeMaxDynamicSharedMemorySize, GEMM_SMEM);
    cudaFuncSetAttribute(attn_kernel,
                         cudaFuncAttributeMaxDynamicSharedMemorySize, ATT_SMEM);

    conv_a_kernel<<<M_, 256>>>(x);
    conv_w_kernel<<<dim3(E_ / 64, QKV_N / 64), 256>>>(Wq, QKV_N, 0);
    conv_w_kernel<<<dim3(E_ / 64, E_ / 64), 256>>>(Wp, E_, 1);

    hgemm_kernel<<<dim3(QKV_N / 128, M_ / 128), 160, GEMM_SMEM>>>(bq, out, 0);

    attn_kernel<<<dim3(N_ / 128, H_, B_), 256, ATT_SMEM>>>();

    hgemm_kernel<<<dim3(E_ / 128, M_ / 128), 160, GEMM_SMEM>>>(bp, out, 1);
}